// round 15
// baseline (speedup 1.0000x reference)
#include <cuda_runtime.h>
#include <math.h>

// ---------------- problem constants ----------------
#define BB   8
#define NN   4096
#define KNB  20
#define NKK  (NN*KNB)
#define EPSV 1e-6f
#define BNEPS 1e-5f

// ---------------- static device scratch (allocation-free) ----------------
__device__ float  g_bufPD[(size_t)BB*682*3*NN];  // stacked P/D (268MB); also stage-1 norms
__device__ int    g_idx [BB*NKK];
__device__ float  g_h   [BB*21*3*NN];
__device__ float  g_h1  [BB*21*3*NN];
__device__ float  g_s1  [BB*21*3*NN];
__device__ float  g_s2  [BB*42*3*NN];
__device__ float  g_s3  [BB*341*3*NN];
__device__ float  g_sp  [BB*341*3];
__device__ float  g_t1  [BB*170*3];
__device__ float  g_t2  [BB*85*3];
__device__ float  g_t3  [BB*21*3];
__device__ float  g_h42c[BB*42*3*NN];
__device__ float  g_c3o [(size_t)BB*341*3*NN];   // c3 combine output (ex-h682 lower half)
__device__ float  g_mean3[BB*341*3];
__device__ float  g_z1  [BB*341*3*NN];
__device__ float  g_z0s [BB*3*3*NN];
__device__ double g_part2[682*64*2];
__device__ float  g_bn  [682*2];
__device__ double g_partd[21*64];
__device__ float  g_bnpos[21*2];
__device__ float  g_wstk[761604];     // stacked [Wf;Wd] for all dual stages

// stacked-weight offsets (floats)
#define OFF_C1   0
#define OFF_ST1  882
#define OFF_ST2  1764
#define OFF_ST3  3528
#define OFF_STF1 32172
#define OFF_STF2 148112
#define OFF_C2   177012
#define OFF_STD1 180540
#define OFF_STD2 645664

// single merged weight-stacking kernel (9 [Wf;Wd] pairs)
__global__ void stack_w_all(const float* __restrict__ a0, const float* __restrict__ b0,
                            const float* __restrict__ a1, const float* __restrict__ b1,
                            const float* __restrict__ a2, const float* __restrict__ b2,
                            const float* __restrict__ a3, const float* __restrict__ b3,
                            const float* __restrict__ a4, const float* __restrict__ b4,
                            const float* __restrict__ a5, const float* __restrict__ b5,
                            const float* __restrict__ a6, const float* __restrict__ b6,
                            const float* __restrict__ a7, const float* __restrict__ b7,
                            const float* __restrict__ a8, const float* __restrict__ b8,
                            float* __restrict__ dst) {
    const int offs[10] = {OFF_C1, OFF_ST1, OFF_ST2, OFF_ST3, OFF_STF1, OFF_STF2,
                          OFF_C2, OFF_STD1, OFF_STD2, 761604};
    const float* fa[9] = {a0,a1,a2,a3,a4,a5,a6,a7,a8};
    const float* fb[9] = {b0,b1,b2,b3,b4,b5,b6,b7,b8};
    int t = blockIdx.x * blockDim.x + threadIdx.x;
    if (t >= 761604) return;
    #pragma unroll
    for (int s = 0; s < 9; s++) {
        if (t >= offs[s] && t < offs[s+1]) {
            int loc = t - offs[s];
            int OC = (offs[s+1] - offs[s]) / 2;
            dst[t] = (loc < OC) ? fa[s][loc] : fb[s][loc - OC];
            return;
        }
    }
}

// ---------------- kNN: f32 prefilter + fp64-truth refine (same selection) -------
__global__ void knn_kernel(const float* __restrict__ x, int* __restrict__ idxout) {
    __shared__ float sx0[NN], sx1[NN], sx2[NN];
    int b = blockIdx.y;
    for (int t = threadIdx.x; t < 3*NN; t += blockDim.x) {
        float v = x[(size_t)b*3*NN + t];
        int d = t / NN, n = t - d*NN;
        if (d == 0) sx0[n] = v; else if (d == 1) sx1[n] = v; else sx2[n] = v;
    }
    __syncthreads();
    int i = blockIdx.x * blockDim.x + threadIdx.x;
    float fxi0 = sx0[i], fxi1 = sx1[i], fxi2 = sx2[i];
    float fxx = fxi0*fxi0 + fxi1*fxi1 + fxi2*fxi2;

    float fv[KNB];
    #pragma unroll
    for (int t = 0; t < KNB; t++) fv[t] = -3.0e38f;
    float fmin = -3.0e38f; int fminp = 0;
    for (int j = 0; j < NN; j++) {
        float a0 = sx0[j], a1 = sx1[j], a2 = sx2[j];
        float dot = fxi0*a0 + fxi1*a1 + fxi2*a2;
        float pd  = 2.f*dot - fxx - (a0*a0 + a1*a1 + a2*a2);
        if (pd > fmin) {
            fv[fminp] = pd; fmin = fv[0]; fminp = 0;
            #pragma unroll
            for (int t = 1; t < KNB; t++)
                if (fv[t] < fmin) { fmin = fv[t]; fminp = t; }
        }
    }
    float thr = fmin - 1e-3f;

    double xi0 = (double)fxi0, xi1 = (double)fxi1, xi2 = (double)fxi2;
    double xxi = xi0*xi0 + xi1*xi1 + xi2*xi2;
    double bv[KNB]; int bi[KNB];
    #pragma unroll
    for (int t = 0; t < KNB; t++) { bv[t] = -1.0e300; bi[t] = 0; }
    double minv = -1.0e300; int minp = 0;
    for (int j = 0; j < NN; j++) {
        float a0 = sx0[j], a1 = sx1[j], a2 = sx2[j];
        float dotf = fxi0*a0 + fxi1*a1 + fxi2*a2;
        float pdf  = 2.f*dotf - fxx - (a0*a0 + a1*a1 + a2*a2);
        if (pdf >= thr) {
            double d0 = (double)a0, d1 = (double)a1, d2 = (double)a2;
            double dot = xi0*d0 + xi1*d1 + xi2*d2;
            double pd  = 2.0*dot - xxi - (d0*d0 + d1*d1 + d2*d2);
            if (pd > minv) {
                bv[minp] = pd; bi[minp] = j;
                minv = bv[0]; minp = 0;
                #pragma unroll
                for (int t = 1; t < KNB; t++)
                    if (bv[t] < minv) { minv = bv[t]; minp = t; }
            }
        }
    }
    int* dst = idxout + ((size_t)b*NN + i)*KNB;
    #pragma unroll
    for (int t = 0; t < KNB; t++) dst[t] = bi[t];
}

// ---- XLA-replica f32 feature build (FROZEN) ------------------------------------
__device__ __forceinline__ void feat_f32(const float* __restrict__ xb, int n, int j,
                                         float* f) {
    float xi0 = xb[n],  xi1 = xb[NN + n],  xi2 = xb[2*NN + n];
    float xj0 = xb[j],  xj1 = xb[NN + j],  xj2 = xb[2*NN + j];
    f[0] = __fsub_rn(xj0, xi0); f[1] = __fsub_rn(xj1, xi1); f[2] = __fsub_rn(xj2, xi2);
    f[3] = xi0; f[4] = xi1; f[5] = xi2;
    f[6] = __fsub_rn(__fmul_rn(xj1, xi2), __fmul_rn(xj2, xi1));
    f[7] = __fsub_rn(__fmul_rn(xj2, xi0), __fmul_rn(xj0, xi2));
    f[8] = __fsub_rn(__fmul_rn(xj0, xi1), __fmul_rn(xj1, xi0));
}

__device__ __forceinline__ float dot3_fma(float w0, float w1, float w2,
                                          float f0, float f1, float f2) {
    float a = __fmul_rn(w0, f0);
    a = __fmaf_rn(w1, f1, a);
    a = __fmaf_rn(w2, f2, a);
    return a;
}

__device__ __forceinline__ float sum3_nofma(float a0, float b0, float a1, float b1,
                                            float a2, float b2) {
    return __fadd_rn(__fadd_rn(__fmul_rn(a0, b0), __fmul_rn(a1, b1)), __fmul_rn(a2, b2));
}

// ---- stage-1: materialize replica norms ONCE (FROZEN values) -------------------
__global__ void pos_norm_kernel(const float* __restrict__ x, const int* __restrict__ idx,
                                const float* __restrict__ Wf, float* __restrict__ norms) {
    const int total = BB*NKK;
    int t = blockIdx.x * blockDim.x + threadIdx.x;
    if (t >= total) return;
    int b = t / NKK, nk = t - (t / NKK)*NKK;
    int n = nk / KNB;
    int j = idx[(size_t)b*NKK + nk];
    const float* xb = x + (size_t)b*3*NN;
    float f[9]; feat_f32(xb, n, j, f);
    #pragma unroll 3
    for (int o = 0; o < 21; o++) {
        float w0 = __ldg(Wf + o*3), w1 = __ldg(Wf + o*3 + 1), w2 = __ldg(Wf + o*3 + 2);
        float p0 = dot3_fma(w0, w1, w2, f[0], f[3], f[6]);
        float p1 = dot3_fma(w0, w1, w2, f[1], f[4], f[7]);
        float p2 = dot3_fma(w0, w1, w2, f[2], f[5], f[8]);
        float nsq = sum3_nofma(p0, p0, p1, p1, p2, p2);
        float nr = __fadd_rn(__fsqrt_rn(nsq), EPSV);
        norms[(size_t)o*total + t] = nr;
    }
}

// stage-1 stats: FROZEN two-pass fp64-accumulate (bit-identical bnpos)
__global__ void bn_pos_mean(const float* __restrict__ norms, int nblk,
                            double* __restrict__ part) {
    int o = blockIdx.x, blk = blockIdx.y;
    const int total = BB*NKK;
    const float* No = norms + (size_t)o*total;
    double s = 0.0;
    for (int t = blk*blockDim.x + threadIdx.x; t < total; t += nblk*blockDim.x)
        s += (double)No[t];
    __shared__ double sh[256];
    sh[threadIdx.x] = s;
    __syncthreads();
    for (int st = 128; st > 0; st >>= 1) {
        if (threadIdx.x < st) sh[threadIdx.x] += sh[threadIdx.x+st];
        __syncthreads();
    }
    if (threadIdx.x == 0) part[(size_t)o*nblk + blk] = sh[0];
}

__global__ void bn_pos_var(const float* __restrict__ norms, const float* __restrict__ bnpos,
                           int nblk, double* __restrict__ part) {
    int o = blockIdx.x, blk = blockIdx.y;
    const int total = BB*NKK;
    const float* No = norms + (size_t)o*total;
    float mean = bnpos[o];
    double s = 0.0;
    for (int t = blk*blockDim.x + threadIdx.x; t < total; t += nblk*blockDim.x) {
        double d = (double)__fsub_rn(No[t], mean);
        s += d*d;
    }
    __shared__ double sh[256];
    sh[threadIdx.x] = s;
    __syncthreads();
    for (int st = 128; st > 0; st >>= 1) {
        if (threadIdx.x < st) sh[threadIdx.x] += sh[threadIdx.x+st];
        __syncthreads();
    }
    if (threadIdx.x == 0) part[(size_t)o*nblk + blk] = sh[0];
}

__global__ void bn_pos_final(const double* __restrict__ part, float* __restrict__ bnpos,
                             int nblk, int cnt, int pass) {
    int o = blockIdx.x;
    __shared__ double s1[64];
    double a = 0.0;
    for (int t = threadIdx.x; t < nblk; t += 64) a += part[(size_t)o*nblk + t];
    s1[threadIdx.x] = a;
    __syncthreads();
    for (int st = 32; st > 0; st >>= 1) {
        if (threadIdx.x < st) s1[threadIdx.x] += s1[threadIdx.x+st];
        __syncthreads();
    }
    if (threadIdx.x == 0) {
        if (pass == 0) bnpos[o] = (float)(s1[0] / cnt);
        else {
            float var = (float)(s1[0] / cnt);
            bnpos[21 + o] = __fsqrt_rn(__fadd_rn(var, BNEPS));
        }
    }
}

// ------- stage-1 replica pool: 4 warps/block, FROZEN per-lane arithmetic --------
__global__ void pool_k_replica(const float* __restrict__ x, const int* __restrict__ idx,
                               const float* __restrict__ Wf, const float* __restrict__ Wd,
                               const float* __restrict__ bnpos,
                               const float* __restrict__ poolWd,
                               float* __restrict__ OutH) {
    int warp = threadIdx.x / 32;
    int lane = threadIdx.x % 32;
    int bnid = blockIdx.x*4 + warp;
    int b = bnid / NN, n = bnid - b*NN;
    __shared__ float hs[4][21][3][KNB];
    __shared__ float wpool[441];
    __shared__ float wf[63], wd[63], bns[42];
    int tid = threadIdx.x;
    for (int t = tid; t < 441; t += blockDim.x) wpool[t] = poolWd[t];
    for (int t = tid; t < 63; t += blockDim.x) { wf[t] = Wf[t]; wd[t] = Wd[t]; }
    for (int t = tid; t < 42; t += blockDim.x) bns[t] = bnpos[t];
    __syncthreads();

    if (lane < KNB) {
        int k = lane;
        int j = idx[(size_t)b*NKK + (size_t)n*KNB + k];
        const float* xb = x + (size_t)b*3*NN;
        float f[9]; feat_f32(xb, n, j, f);
        for (int o = 0; o < 21; o++) {
            float a0 = wf[o*3], a1 = wf[o*3+1], a2 = wf[o*3+2];
            float p0 = dot3_fma(a0, a1, a2, f[0], f[3], f[6]);
            float p1 = dot3_fma(a0, a1, a2, f[1], f[4], f[7]);
            float p2 = dot3_fma(a0, a1, a2, f[2], f[5], f[8]);
            float nsq = sum3_nofma(p0, p0, p1, p1, p2, p2);
            float nr = __fadd_rn(__fsqrt_rn(nsq), EPSV);
            float nbn = __fdiv_rn(__fsub_rn(nr, bns[o]), bns[21 + o]);
            float q0 = __fmul_rn(__fdiv_rn(p0, nr), nbn);
            float q1 = __fmul_rn(__fdiv_rn(p1, nr), nbn);
            float q2 = __fmul_rn(__fdiv_rn(p2, nr), nbn);
            float c0 = wd[o*3], c1 = wd[o*3+1], c2 = wd[o*3+2];
            float d0 = dot3_fma(c0, c1, c2, f[0], f[3], f[6]);
            float d1 = dot3_fma(c0, c1, c2, f[1], f[4], f[7]);
            float d2 = dot3_fma(c0, c1, c2, f[2], f[5], f[8]);
            float dotv = sum3_nofma(q0, d0, q1, d1, q2, d2);
            float dsq  = sum3_nofma(d0, d0, d1, d1, d2, d2);
            if (!(dotv >= 0.f)) {
                float coef = __fdiv_rn(dotv, __fadd_rn(dsq, EPSV));
                q0 = __fsub_rn(q0, __fmul_rn(coef, d0));
                q1 = __fsub_rn(q1, __fmul_rn(coef, d1));
                q2 = __fsub_rn(q2, __fmul_rn(coef, d2));
            }
            hs[warp][o][0][k] = q0; hs[warp][o][1][k] = q1; hs[warp][o][2][k] = q2;
        }
    }
    __syncthreads();
    if (lane < 21) {
        int o = lane;
        float bestdot = -3.0e38f; int bestk = 0;
        for (int k = 0; k < KNB; k++) {
            float d0 = __fmul_rn(wpool[o*21], hs[warp][0][0][k]);
            float d1 = __fmul_rn(wpool[o*21], hs[warp][0][1][k]);
            float d2 = __fmul_rn(wpool[o*21], hs[warp][0][2][k]);
            for (int c = 1; c < 21; c++) {
                float w = wpool[o*21 + c];
                d0 = __fmaf_rn(w, hs[warp][c][0][k], d0);
                d1 = __fmaf_rn(w, hs[warp][c][1][k], d1);
                d2 = __fmaf_rn(w, hs[warp][c][2][k], d2);
            }
            float dotv = sum3_nofma(hs[warp][o][0][k], d0, hs[warp][o][1][k], d1,
                                    hs[warp][o][2][k], d2);
            if (dotv > bestdot) { bestdot = dotv; bestk = k; }
        }
        #pragma unroll
        for (int v = 0; v < 3; v++)
            OutH[((size_t)(b*21 + o)*3 + v)*NN + n] = hs[warp][o][v][bestk];
    }
}

// ------ channel GEMM: 128x128 tile, conflict-free 2x2-quad micro, double-buffer --
__global__ __launch_bounds__(256) void gemm_vn8(const float* __restrict__ W,
                                                const float* __restrict__ X,
                                                float* __restrict__ Y, int O, int C, int J) {
    const float* Xb = X + (size_t)blockIdx.z * C * J;
    float*       Yb = Y + (size_t)blockIdx.z * O * J;
    int row0 = blockIdx.y * 128;
    int col0 = blockIdx.x * 128;
    __shared__ __align__(16) float Ws[2][16][132];
    __shared__ __align__(16) float Xs[2][16][132];
    int tid = threadIdx.x;
    int tx = tid % 16, ty = tid / 16;
    int wc = tid % 16, wr8 = tid / 16;
    int xc = (tid % 32) * 4, xr = tid / 32;
    float acc[8][8] = {};
    int nkt = (C + 15) / 16;

    float wreg[8];
    float4 xreg[2];
    {
        #pragma unroll
        for (int q = 0; q < 8; q++) {
            int o = row0 + wr8*8 + q; int cc = wc;
            wreg[q] = (o < O && cc < C) ? W[(size_t)o*C + cc] : 0.f;
        }
        #pragma unroll
        for (int q = 0; q < 2; q++) {
            int cc = xr + q*8;
            xreg[q] = (cc < C) ? *(const float4*)(Xb + (size_t)cc*J + col0 + xc)
                               : make_float4(0.f, 0.f, 0.f, 0.f);
        }
        #pragma unroll
        for (int q = 0; q < 8; q++) Ws[0][wc][wr8*8 + q] = wreg[q];
        #pragma unroll
        for (int q = 0; q < 2; q++) *(float4*)&Xs[0][xr + q*8][xc] = xreg[q];
    }
    __syncthreads();

    for (int kt = 0; kt < nkt; kt++) {
        int cur = kt & 1;
        if (kt + 1 < nkt) {
            int k0 = (kt + 1) * 16;
            #pragma unroll
            for (int q = 0; q < 8; q++) {
                int o = row0 + wr8*8 + q; int cc = k0 + wc;
                wreg[q] = (o < O && cc < C) ? W[(size_t)o*C + cc] : 0.f;
            }
            #pragma unroll
            for (int q = 0; q < 2; q++) {
                int cc = k0 + xr + q*8;
                xreg[q] = (cc < C) ? *(const float4*)(Xb + (size_t)cc*J + col0 + xc)
                                   : make_float4(0.f, 0.f, 0.f, 0.f);
            }
        }
        #pragma unroll
        for (int kk = 0; kk < 16; kk++) {
            float4 wa = *(const float4*)&Ws[cur][kk][ty*4];
            float4 wb = *(const float4*)&Ws[cur][kk][64 + ty*4];
            float4 xa = *(const float4*)&Xs[cur][kk][tx*4];
            float4 xb4 = *(const float4*)&Xs[cur][kk][64 + tx*4];
            float wv[8] = {wa.x, wa.y, wa.z, wa.w, wb.x, wb.y, wb.z, wb.w};
            float xv[8] = {xa.x, xa.y, xa.z, xa.w, xb4.x, xb4.y, xb4.z, xb4.w};
            #pragma unroll
            for (int a = 0; a < 8; a++)
                #pragma unroll
                for (int bq = 0; bq < 8; bq++)
                    acc[a][bq] += wv[a]*xv[bq];
        }
        if (kt + 1 < nkt) {
            int nxt = (kt + 1) & 1;
            #pragma unroll
            for (int q = 0; q < 8; q++) Ws[nxt][wc][wr8*8 + q] = wreg[q];
            #pragma unroll
            for (int q = 0; q < 2; q++) *(float4*)&Xs[nxt][xr + q*8][xc] = xreg[q];
        }
        __syncthreads();
    }

    #pragma unroll
    for (int rg = 0; rg < 2; rg++) {
        #pragma unroll
        for (int q = 0; q < 4; q++) {
            int o = row0 + rg*64 + ty*4 + q;
            if (o < O) {
                #pragma unroll
                for (int cg = 0; cg < 2; cg++) {
                    int col = col0 + cg*64 + tx*4;
                    float4 v = make_float4(acc[rg*4+q][cg*4], acc[rg*4+q][cg*4+1],
                                           acc[rg*4+q][cg*4+2], acc[rg*4+q][cg*4+3]);
                    *(float4*)(Yb + (size_t)o*J + col) = v;
                }
            }
        }
    }
}

// variant: X channels >= Csplit are broadcast scalars from Mn (b, C-Csplit, 3),
// constant over m. Values identical to a pre-concatenated X.
__global__ __launch_bounds__(256) void gemm_vn8m(const float* __restrict__ W,
                                                 const float* __restrict__ Xa,
                                                 const float* __restrict__ Mn,
                                                 int Csplit,
                                                 float* __restrict__ Y, int O, int C, int J) {
    int M = J / 3;
    const float* Xb  = Xa + (size_t)blockIdx.z * Csplit * J;
    const float* Mnb = Mn + (size_t)blockIdx.z * (C - Csplit) * 3;
    float*       Yb  = Y  + (size_t)blockIdx.z * O * J;
    int row0 = blockIdx.y * 128;
    int col0 = blockIdx.x * 128;
    int vsec = col0 / M;                          // tile lies in one v section
    __shared__ __align__(16) float Ws[2][16][132];
    __shared__ __align__(16) float Xs[2][16][132];
    int tid = threadIdx.x;
    int tx = tid % 16, ty = tid / 16;
    int wc = tid % 16, wr8 = tid / 16;
    int xc = (tid % 32) * 4, xr = tid / 32;
    float acc[8][8] = {};
    int nkt = (C + 15) / 16;

    float wreg[8];
    float4 xreg[2];
    {
        #pragma unroll
        for (int q = 0; q < 8; q++) {
            int o = row0 + wr8*8 + q; int cc = wc;
            wreg[q] = (o < O && cc < C) ? W[(size_t)o*C + cc] : 0.f;
        }
        #pragma unroll
        for (int q = 0; q < 2; q++) {
            int cc = xr + q*8;
            if (cc < Csplit)
                xreg[q] = *(const float4*)(Xb + (size_t)cc*J + col0 + xc);
            else if (cc < C) {
                float mv = Mnb[(cc - Csplit)*3 + vsec];
                xreg[q] = make_float4(mv, mv, mv, mv);
            } else xreg[q] = make_float4(0.f, 0.f, 0.f, 0.f);
        }
        #pragma unroll
        for (int q = 0; q < 8; q++) Ws[0][wc][wr8*8 + q] = wreg[q];
        #pragma unroll
        for (int q = 0; q < 2; q++) *(float4*)&Xs[0][xr + q*8][xc] = xreg[q];
    }
    __syncthreads();

    for (int kt = 0; kt < nkt; kt++) {
        int cur = kt & 1;
        if (kt + 1 < nkt) {
            int k0 = (kt + 1) * 16;
            #pragma unroll
            for (int q = 0; q < 8; q++) {
                int o = row0 + wr8*8 + q; int cc = k0 + wc;
                wreg[q] = (o < O && cc < C) ? W[(size_t)o*C + cc] : 0.f;
            }
            #pragma unroll
            for (int q = 0; q < 2; q++) {
                int cc = k0 + xr + q*8;
                if (cc < Csplit)
                    xreg[q] = *(const float4*)(Xb + (size_t)cc*J + col0 + xc);
                else if (cc < C) {
                    float mv = Mnb[(cc - Csplit)*3 + vsec];
                    xreg[q] = make_float4(mv, mv, mv, mv);
                } else xreg[q] = make_float4(0.f, 0.f, 0.f, 0.f);
            }
        }
        #pragma unroll
        for (int kk = 0; kk < 16; kk++) {
            float4 wa = *(const float4*)&Ws[cur][kk][ty*4];
            float4 wb = *(const float4*)&Ws[cur][kk][64 + ty*4];
            float4 xa = *(const float4*)&Xs[cur][kk][tx*4];
            float4 xb4 = *(const float4*)&Xs[cur][kk][64 + tx*4];
            float wv[8] = {wa.x, wa.y, wa.z, wa.w, wb.x, wb.y, wb.z, wb.w};
            float xv[8] = {xa.x, xa.y, xa.z, xa.w, xb4.x, xb4.y, xb4.z, xb4.w};
            #pragma unroll
            for (int a = 0; a < 8; a++)
                #pragma unroll
                for (int bq = 0; bq < 8; bq++)
                    acc[a][bq] += wv[a]*xv[bq];
        }
        if (kt + 1 < nkt) {
            int nxt = (kt + 1) & 1;
            #pragma unroll
            for (int q = 0; q < 8; q++) Ws[nxt][wc][wr8*8 + q] = wreg[q];
            #pragma unroll
            for (int q = 0; q < 2; q++) *(float4*)&Xs[nxt][xr + q*8][xc] = xreg[q];
        }
        __syncthreads();
    }

    #pragma unroll
    for (int rg = 0; rg < 2; rg++) {
        #pragma unroll
        for (int q = 0; q < 4; q++) {
            int o = row0 + rg*64 + ty*4 + q;
            if (o < O) {
                #pragma unroll
                for (int cg = 0; cg < 2; cg++) {
                    int col = col0 + cg*64 + tx*4;
                    float4 v = make_float4(acc[rg*4+q][cg*4], acc[rg*4+q][cg*4+1],
                                           acc[rg*4+q][cg*4+2], acc[rg*4+q][cg*4+3]);
                    *(float4*)(Yb + (size_t)o*J + col) = v;
                }
            }
        }
    }
}

// small GEMM: one thread per output, ascending-c serial (bit-identical order)
__global__ void gemm_small(const float* __restrict__ W, const float* __restrict__ X,
                           float* __restrict__ Y, int O, int C, int J) {
    size_t total = (size_t)BB*O*J;
    size_t t = (size_t)blockIdx.x * blockDim.x + threadIdx.x;
    if (t >= total) return;
    int col = t % J; size_t r = t / J; int o = r % O; int b = r / O;
    const float* Xb = X + (size_t)b*C*J + col;
    const float* Wo = W + (size_t)o*C;
    float acc = 0.f;
    for (int c = 0; c < C; c++) acc += Wo[c]*Xb[(size_t)c*J];
    Y[(size_t)b*O*J + (size_t)o*J + col] = acc;
}

// ---------------- downstream BN stats: single pass sum+sumsq, float4 ------------
__global__ void bn_stats2v(const float* __restrict__ Y, int O, int M, size_t bstride,
                           int BM4, int nblk, double* __restrict__ part) {
    int o = blockIdx.x, blk = blockIdx.y;
    int M4 = M / 4;
    double s = 0.0, s2 = 0.0;
    for (int t = blk*blockDim.x + threadIdx.x; t < BM4; t += nblk*blockDim.x) {
        int b = t / M4; int m4 = t - b*M4;
        const float* base = Y + (size_t)b*bstride + ((size_t)o*3)*M + m4*4;
        float4 v0 = *(const float4*)(base);
        float4 v1 = *(const float4*)(base + M);
        float4 v2 = *(const float4*)(base + 2*(size_t)M);
        float nr;
        nr = sqrtf(v0.x*v0.x + v1.x*v1.x + v2.x*v2.x) + EPSV; s += (double)nr; s2 += (double)nr*(double)nr;
        nr = sqrtf(v0.y*v0.y + v1.y*v1.y + v2.y*v2.y) + EPSV; s += (double)nr; s2 += (double)nr*(double)nr;
        nr = sqrtf(v0.z*v0.z + v1.z*v1.z + v2.z*v2.z) + EPSV; s += (double)nr; s2 += (double)nr*(double)nr;
        nr = sqrtf(v0.w*v0.w + v1.w*v1.w + v2.w*v2.w) + EPSV; s += (double)nr; s2 += (double)nr*(double)nr;
    }
    __shared__ double sh1[256], sh2[256];
    sh1[threadIdx.x] = s; sh2[threadIdx.x] = s2;
    __syncthreads();
    for (int st = 128; st > 0; st >>= 1) {
        if (threadIdx.x < st) { sh1[threadIdx.x] += sh1[threadIdx.x+st]; sh2[threadIdx.x] += sh2[threadIdx.x+st]; }
        __syncthreads();
    }
    if (threadIdx.x == 0) {
        part[((size_t)o*nblk + blk)*2]     = sh1[0];
        part[((size_t)o*nblk + blk)*2 + 1] = sh2[0];
    }
}

__global__ void bn_stats2(const float* __restrict__ Y, int O, int M, size_t bstride,
                          int BMtot, int nblk, double* __restrict__ part) {
    int o = blockIdx.x, blk = blockIdx.y;
    double s = 0.0, s2 = 0.0;
    for (int t = blk*blockDim.x + threadIdx.x; t < BMtot; t += nblk*blockDim.x) {
        int b = t / M; int m = t - b*M;
        const float* base = Y + (size_t)b*bstride + ((size_t)o*3)*M + m;
        float v0 = base[0], v1 = base[M], v2 = base[2*(size_t)M];
        float nr = sqrtf(v0*v0 + v1*v1 + v2*v2) + EPSV;
        s += (double)nr; s2 += (double)nr*(double)nr;
    }
    __shared__ double sh1[256], sh2[256];
    sh1[threadIdx.x] = s; sh2[threadIdx.x] = s2;
    __syncthreads();
    for (int st = 128; st > 0; st >>= 1) {
        if (threadIdx.x < st) { sh1[threadIdx.x] += sh1[threadIdx.x+st]; sh2[threadIdx.x] += sh2[threadIdx.x+st]; }
        __syncthreads();
    }
    if (threadIdx.x == 0) {
        part[((size_t)o*nblk + blk)*2]     = sh1[0];
        part[((size_t)o*nblk + blk)*2 + 1] = sh2[0];
    }
}

__global__ void bn_final2(const double* __restrict__ part, float* __restrict__ bn,
                          int O, int nblk, int cnt) {
    int o = blockIdx.x;
    __shared__ double s1[64], s2[64];
    double a = 0.0, c = 0.0;
    for (int t = threadIdx.x; t < nblk; t += 64) {
        a += part[((size_t)o*nblk + t)*2];
        c += part[((size_t)o*nblk + t)*2 + 1];
    }
    s1[threadIdx.x] = a; s2[threadIdx.x] = c;
    __syncthreads();
    for (int st = 32; st > 0; st >>= 1) {
        if (threadIdx.x < st) { s1[threadIdx.x] += s1[threadIdx.x+st]; s2[threadIdx.x] += s2[threadIdx.x+st]; }
        __syncthreads();
    }
    if (threadIdx.x == 0) {
        double mean = s1[0] / cnt;
        double var  = s2[0] / cnt - mean*mean;
        bn[o]     = (float)mean;
        bn[O + o] = (float)(1.0 / sqrt(var + (double)BNEPS));
    }
}

// ---------------- BN apply (+ optional lrelu), float4 ---------------------------
__global__ void vn_combine4(const float* __restrict__ P, const float* __restrict__ D,
                            const float* __restrict__ bn, float* __restrict__ Out,
                            int O, int M, int lrelu, size_t bstride) {
    int M4 = M / 4;
    int total = BB*O*M4;
    int t = blockIdx.x * blockDim.x + threadIdx.x;
    if (t >= total) return;
    int m4 = t % M4; int r = t / M4; int o = r % O; int b = r / O;
    int m = m4*4;
    size_t bin = (size_t)b*bstride + ((size_t)o*3)*M + m;
    size_t bout = ((size_t)(b*O + o)*3)*M + m;
    float4 p0 = *(const float4*)(P + bin);
    float4 p1 = *(const float4*)(P + bin + M);
    float4 p2 = *(const float4*)(P + bin + 2*(size_t)M);
    float4 d0 = *(const float4*)(D + bin);
    float4 d1 = *(const float4*)(D + bin + M);
    float4 d2 = *(const float4*)(D + bin + 2*(size_t)M);
    float mean = bn[o], inv = bn[O + o];
    float o0[4], o1[4], o2[4];
    float pp0[4] = {p0.x, p0.y, p0.z, p0.w};
    float pp1[4] = {p1.x, p1.y, p1.z, p1.w};
    float pp2[4] = {p2.x, p2.y, p2.z, p2.w};
    float dd0[4] = {d0.x, d0.y, d0.z, d0.w};
    float dd1[4] = {d1.x, d1.y, d1.z, d1.w};
    float dd2[4] = {d2.x, d2.y, d2.z, d2.w};
    #pragma unroll
    for (int q = 0; q < 4; q++) {
        float q0 = pp0[q], q1 = pp1[q], q2 = pp2[q];
        float nr = sqrtf(q0*q0 + q1*q1 + q2*q2) + EPSV;
        float sc = (nr - mean) * inv / nr;
        q0 *= sc; q1 *= sc; q2 *= sc;
        if (lrelu) {
            float e0 = dd0[q], e1 = dd1[q], e2 = dd2[q];
            float dotv = q0*e0 + q1*e1 + q2*e2;
            if (dotv < 0.f) {
                float coef = dotv / (e0*e0 + e1*e1 + e2*e2 + EPSV);
                q0 -= coef*e0; q1 -= coef*e1; q2 -= coef*e2;
            }
        }
        o0[q] = q0; o1[q] = q1; o2[q] = q2;
    }
    *(float4*)(Out + bout)              = make_float4(o0[0], o0[1], o0[2], o0[3]);
    *(float4*)(Out + bout + M)          = make_float4(o1[0], o1[1], o1[2], o1[3]);
    *(float4*)(Out + bout + 2*(size_t)M)= make_float4(o2[0], o2[1], o2[2], o2[3]);
}

__global__ void vn_combine(const float* __restrict__ P, const float* __restrict__ D,
                           const float* __restrict__ bn, float* __restrict__ Out,
                           int O, int M, int lrelu, size_t bstride) {
    int total = BB*O*M;
    int t = blockIdx.x * blockDim.x + threadIdx.x;
    if (t >= total) return;
    int m = t % M; int r = t / M; int o = r % O; int b = r / O;
    size_t bin = (size_t)b*bstride + ((size_t)o*3)*M + m;
    size_t bout = ((size_t)(b*O + o)*3)*M + m;
    float p0 = P[bin], p1 = P[bin + M], p2 = P[bin + 2*(size_t)M];
    float nr = sqrtf(p0*p0 + p1*p1 + p2*p2) + EPSV;
    float sc = (nr - bn[o]) * bn[O + o] / nr;
    p0 *= sc; p1 *= sc; p2 *= sc;
    if (lrelu) {
        float d0 = D[bin], d1 = D[bin + M], d2 = D[bin + 2*(size_t)M];
        float dot = p0*d0 + p1*d1 + p2*d2;
        if (dot < 0.f) {
            float coef = dot / (d0*d0 + d1*d1 + d2*d2 + EPSV);
            p0 -= coef*d0; p1 -= coef*d1; p2 -= coef*d2;
        }
    }
    Out[bout] = p0; Out[bout + M] = p1; Out[bout + 2*(size_t)M] = p2;
}

// ---------------- VN max-pool over N (fp64 keys) ---------------------------------
__global__ void pool_n_kernel(const float* __restrict__ S, const float* __restrict__ Dv,
                              float* __restrict__ Out) {
    int bc = blockIdx.x;
    const float* Sb = S  + (size_t)bc*3*NN;
    const float* Db = Dv + (size_t)bc*3*NN;
    double bestv = -1.0e300; int besti = NN;
    for (int n = threadIdx.x; n < NN; n += 256) {
        double dot = (double)Sb[n]*(double)Db[n]
                   + (double)Sb[NN+n]*(double)Db[NN+n]
                   + (double)Sb[2*NN+n]*(double)Db[2*NN+n];
        if (dot > bestv || (dot == bestv && n < besti)) { bestv = dot; besti = n; }
    }
    __shared__ double sv[256]; __shared__ int si[256];
    sv[threadIdx.x] = bestv; si[threadIdx.x] = besti;
    __syncthreads();
    for (int st = 128; st > 0; st >>= 1) {
        if (threadIdx.x < st) {
            if (sv[threadIdx.x+st] > sv[threadIdx.x] ||
                (sv[threadIdx.x+st] == sv[threadIdx.x] && si[threadIdx.x+st] < si[threadIdx.x])) {
                sv[threadIdx.x] = sv[threadIdx.x+st]; si[threadIdx.x] = si[threadIdx.x+st];
            }
        }
        __syncthreads();
    }
    if (threadIdx.x == 0) {
        int n = si[0];
        for (int v = 0; v < 3; v++) Out[(size_t)bc*3 + v] = Sb[(size_t)v*NN + n];
    }
}

// ---------------- mean over N (float4 reads, double accumulate) ------------------
__global__ void mean_n_kernel(const float* __restrict__ X, float* __restrict__ Out) {
    int row = blockIdx.x;
    const float* Xr = X + (size_t)row*NN;
    double s = 0.0;
    for (int n4 = threadIdx.x; n4 < NN/4; n4 += 256) {
        float4 v = *(const float4*)(Xr + n4*4);
        s += (double)v.x + (double)v.y + (double)v.z + (double)v.w;
    }
    __shared__ double sh[256];
    sh[threadIdx.x] = s;
    __syncthreads();
    for (int st = 128; st > 0; st >>= 1) {
        if (threadIdx.x < st) sh[threadIdx.x] += sh[threadIdx.x+st];
        __syncthreads();
    }
    if (threadIdx.x == 0) Out[row] = (float)(sh[0] / (double)NN);
}

// --------- final: split-source (C3 rows + mean rows), float4, global max --------
__global__ void final_max_kernel(const float* __restrict__ C3, const float* __restrict__ Mn,
                                 const float* __restrict__ Z, float* __restrict__ out) {
    int bi = blockIdx.x; int b = bi / 682; int i = bi - b*682;
    const float* Zb = Z + (size_t)b*9*NN;
    float m0 = -3.0e38f, m1 = -3.0e38f, m2 = -3.0e38f;
    if (i < 341) {
        const float* Hb = C3 + ((size_t)(b*341 + i)*3)*NN;
        for (int n4 = threadIdx.x; n4 < NN/4; n4 += 128) {
            int n = n4*4;
            float4 h0 = *(const float4*)(Hb + n);
            float4 h1 = *(const float4*)(Hb + NN + n);
            float4 h2 = *(const float4*)(Hb + 2*NN + n);
            float4 z0 = *(const float4*)(Zb + 0*NN + n);
            float4 z1 = *(const float4*)(Zb + 1*NN + n);
            float4 z2 = *(const float4*)(Zb + 2*NN + n);
            float4 z3 = *(const float4*)(Zb + 3*NN + n);
            float4 z4 = *(const float4*)(Zb + 4*NN + n);
            float4 z5 = *(const float4*)(Zb + 5*NN + n);
            float4 z6 = *(const float4*)(Zb + 6*NN + n);
            float4 z7 = *(const float4*)(Zb + 7*NN + n);
            float4 z8 = *(const float4*)(Zb + 8*NN + n);
            float hh0[4] = {h0.x,h0.y,h0.z,h0.w};
            float hh1[4] = {h1.x,h1.y,h1.z,h1.w};
            float hh2[4] = {h2.x,h2.y,h2.z,h2.w};
            float zz0[4] = {z0.x,z0.y,z0.z,z0.w};
            float zz1[4] = {z1.x,z1.y,z1.z,z1.w};
            float zz2[4] = {z2.x,z2.y,z2.z,z2.w};
            float zz3[4] = {z3.x,z3.y,z3.z,z3.w};
            float zz4[4] = {z4.x,z4.y,z4.z,z4.w};
            float zz5[4] = {z5.x,z5.y,z5.z,z5.w};
            float zz6[4] = {z6.x,z6.y,z6.z,z6.w};
            float zz7[4] = {z7.x,z7.y,z7.z,z7.w};
            float zz8[4] = {z8.x,z8.y,z8.z,z8.w};
            #pragma unroll
            for (int q = 0; q < 4; q++) {
                float s0 = hh0[q]*zz0[q] + hh1[q]*zz3[q] + hh2[q]*zz6[q];
                float s1 = hh0[q]*zz1[q] + hh1[q]*zz4[q] + hh2[q]*zz7[q];
                float s2 = hh0[q]*zz2[q] + hh1[q]*zz5[q] + hh2[q]*zz8[q];
                m0 = fmaxf(m0, s0); m1 = fmaxf(m1, s1); m2 = fmaxf(m2, s2);
            }
        }
    } else {
        float hm0 = Mn[((size_t)b*341 + (i-341))*3 + 0];
        float hm1 = Mn[((size_t)b*341 + (i-341))*3 + 1];
        float hm2 = Mn[((size_t)b*341 + (i-341))*3 + 2];
        for (int n = threadIdx.x; n < NN; n += 128) {
            float s0 = hm0*Zb[0*NN+n] + hm1*Zb[3*NN+n] + hm2*Zb[6*NN+n];
            float s1 = hm0*Zb[1*NN+n] + hm1*Zb[4*NN+n] + hm2*Zb[7*NN+n];
            float s2 = hm0*Zb[2*NN+n] + hm1*Zb[5*NN+n] + hm2*Zb[8*NN+n];
            m0 = fmaxf(m0, s0); m1 = fmaxf(m1, s1); m2 = fmaxf(m2, s2);
        }
    }
    __shared__ float sm[3][128];
    sm[0][threadIdx.x] = m0; sm[1][threadIdx.x] = m1; sm[2][threadIdx.x] = m2;
    __syncthreads();
    for (int st = 64; st > 0; st >>= 1) {
        if (threadIdx.x < st) {
            sm[0][threadIdx.x] = fmaxf(sm[0][threadIdx.x], sm[0][threadIdx.x+st]);
            sm[1][threadIdx.x] = fmaxf(sm[1][threadIdx.x], sm[1][threadIdx.x+st]);
            sm[2][threadIdx.x] = fmaxf(sm[2][threadIdx.x], sm[2][threadIdx.x+st]);
        }
        __syncthreads();
    }
    if (threadIdx.x < 3) out[(size_t)b*2046 + i*3 + threadIdx.x] = sm[threadIdx.x][0];
}

// ---------------- host helpers ---------------------------------------------------
static inline int cdiv(int a, int b) { return (a + b - 1) / b; }
static float* symf(const void* s) { void* p = 0; cudaGetSymbolAddress(&p, s); return (float*)p; }

static void gemm8_launch(const float* W, const float* X, float* Y, int O, int C, int J) {
    if (O <= 24 || J < 128 || (J % 128) != 0) {
        size_t total = (size_t)BB*O*J;
        gemm_small<<<(int)((total + 255)/256), 256>>>(W, X, Y, O, C, J);
    } else {
        dim3 grid(J/128, cdiv(O, 128), BB);
        gemm_vn8<<<grid, 256>>>(W, X, Y, O, C, J);
    }
}

static void bn_launch2(const float* Y, int O, int M, size_t bstride,
                       double* part2, float* bn) {
    int BMtot = BB * M;
    int nblk = BMtot / 8192; if (nblk < 1) nblk = 1; if (nblk > 64) nblk = 64;
    if (M % 4 == 0)
        bn_stats2v<<<dim3(O, nblk), 256>>>(Y, O, M, bstride, BMtot/4, nblk, part2);
    else
        bn_stats2<<<dim3(O, nblk), 256>>>(Y, O, M, bstride, BMtot, nblk, part2);
    bn_final2<<<O, 64>>>(part2, bn, O, nblk, BMtot);
}

static void combine_launch(const float* P, const float* D, const float* bn,
                           float* Out, int O, int M, int lrelu, size_t bstride) {
    if (M % 4 == 0) {
        int total = BB * O * (M/4);
        vn_combine4<<<cdiv(total, 256), 256>>>(P, D, bn, Out, O, M, lrelu, bstride);
    } else {
        int total = BB * O * M;
        vn_combine<<<cdiv(total, 256), 256>>>(P, D, bn, Out, O, M, lrelu, bstride);
    }
}

static void lrelu_stage2(const float* Wstk, const float* X, float* outb,
                         int O, int C, int M, float* bufPD,
                         double* part2, float* bn) {
    int J = 3*M;
    gemm8_launch(Wstk, X, bufPD, 2*O, C, J);
    size_t bs = (size_t)2*O*3*M;
    bn_launch2(bufPD, O, M, bs, part2, bn);
    combine_launch(bufPD, bufPD + (size_t)O*3*M, bn, outb, O, M, 1, bs);
}

// dual stage with broadcast upper channels (Mn constant over m)
static void lrelu_stage2m(const float* Wstk, const float* Xa, const float* Mn, int Csplit,
                          float* outb, int O, int C, int M, float* bufPD,
                          double* part2, float* bn) {
    int J = 3*M;
    dim3 grid(J/128, cdiv(2*O, 128), BB);
    gemm_vn8m<<<grid, 256>>>(Wstk, Xa, Mn, Csplit, bufPD, 2*O, C, J);
    size_t bs = (size_t)2*O*3*M;
    bn_launch2(bufPD, O, M, bs, part2, bn);
    combine_launch(bufPD, bufPD + (size_t)O*3*M, bn, outb, O, M, 1, bs);
}

extern "C" void kernel_launch(void* const* d_in, const int* in_sizes, int n_in,
                              void* d_out, int out_size) {
    const float* x          = (const float*)d_in[0];
    const float* pos_Wf     = (const float*)d_in[1];
    const float* pos_Wd     = (const float*)d_in[2];
    const float* pool_Wd    = (const float*)d_in[3];
    const float* c1_Wf      = (const float*)d_in[4];
    const float* c1_Wd      = (const float*)d_in[5];
    const float* st1_Wf     = (const float*)d_in[6];
    const float* st1_Wd     = (const float*)d_in[7];
    const float* st2_Wf     = (const float*)d_in[8];
    const float* st2_Wd     = (const float*)d_in[9];
    const float* st3_Wf     = (const float*)d_in[10];
    const float* st3_Wd     = (const float*)d_in[11];
    const float* st_pool_Wd = (const float*)d_in[12];
    const float* stf1_Wf    = (const float*)d_in[13];
    const float* stf1_Wd    = (const float*)d_in[14];
    const float* stf2_Wf    = (const float*)d_in[15];
    const float* stf2_Wd    = (const float*)d_in[16];
    const float* stf3_W     = (const float*)d_in[17];
    const float* c2_Wf      = (const float*)d_in[18];
    const float* c2_Wd      = (const float*)d_in[19];
    const float* c3_W       = (const float*)d_in[20];
    const float* std1_Wf    = (const float*)d_in[21];
    const float* std1_Wd    = (const float*)d_in[22];
    const float* std2_Wf    = (const float*)d_in[23];
    const float* std2_Wd    = (const float*)d_in[24];
    const float* std_lin    = (const float*)d_in[25];

    float*  bufPD = symf(g_bufPD);
    int*    idxp; { void* p=0; cudaGetSymbolAddress(&p, g_idx); idxp = (int*)p; }
    float*  hbuf  = symf(g_h);
    float*  h1b   = symf(g_h1);
    float*  s1b   = symf(g_s1);
    float*  s2b   = symf(g_s2);
    float*  s3b   = symf(g_s3);
    float*  spb   = symf(g_sp);
    float*  t1b   = symf(g_t1);
    float*  t2b   = symf(g_t2);
    float*  t3b   = symf(g_t3);
    float*  h42c  = symf(g_h42c);
    float*  c3o   = symf(g_c3o);
    float*  mn3   = symf(g_mean3);
    float*  z1b   = symf(g_z1);
    float*  z0sc  = symf(g_z0s);
    float*  bn    = symf(g_bn);
    float*  bnpos = symf(g_bnpos);
    float*  wstk  = symf(g_wstk);
    double* partd;  { void* p=0; cudaGetSymbolAddress(&p, g_partd);  partd  = (double*)p; }
    double* part2;  { void* p=0; cudaGetSymbolAddress(&p, g_part2);  part2  = (double*)p; }

    float* outf = (float*)d_out;
    const int OUT1 = BB*2046;
    const int OUTZ = BB*9*NN;
    float* z0dst = (out_size >= OUT1 + OUTZ) ? (outf + OUT1) : z0sc;

    // 0. stack dual weights [Wf;Wd] — single kernel
    stack_w_all<<<cdiv(761604, 256), 256>>>(c1_Wf, c1_Wd, st1_Wf, st1_Wd, st2_Wf, st2_Wd,
                                            st3_Wf, st3_Wd, stf1_Wf, stf1_Wd,
                                            stf2_Wf, stf2_Wd, c2_Wf, c2_Wd,
                                            std1_Wf, std1_Wd, std2_Wf, std2_Wd, wstk);

    // 1. kNN (f32 prefilter + fp64 refine, same selection)
    knn_kernel<<<dim3(NN/128, BB), 128>>>(x, idxp);

    // 2. stage 1 (FROZEN values): norms once, two-pass stats, replica pool
    {
        const int total = BB*NKK;
        const int nblk = 64;
        pos_norm_kernel<<<cdiv(total, 256), 256>>>(x, idxp, pos_Wf, bufPD);
        bn_pos_mean<<<dim3(21, nblk), 256>>>(bufPD, nblk, partd);
        bn_pos_final<<<21, 64>>>(partd, bnpos, nblk, total, 0);
        bn_pos_var<<<dim3(21, nblk), 256>>>(bufPD, bnpos, nblk, partd);
        bn_pos_final<<<21, 64>>>(partd, bnpos, nblk, total, 1);
        pool_k_replica<<<BB*NN/4, 128>>>(x, idxp, pos_Wf, pos_Wd, bnpos, pool_Wd, hbuf);
    }

    // 3. conv1 + STN trunk (stacked dual gemms)
    lrelu_stage2(wstk + OFF_C1,  hbuf, h1b, 21, 21, NN, bufPD, part2, bn);
    lrelu_stage2(wstk + OFF_ST1, h1b,  s1b, 21, 21, NN, bufPD, part2, bn);
    lrelu_stage2(wstk + OFF_ST2, s1b,  s2b, 42, 21, NN, bufPD, part2, bn);
    lrelu_stage2(wstk + OFF_ST3, s2b,  s3b, 341, 42, NN, bufPD, part2, bn);

    // 4. STN pool over N
    gemm8_launch(st_pool_Wd, s3b, bufPD, 341, 341, 3*NN);
    pool_n_kernel<<<BB*341, 256>>>(s3b, bufPD, spb);

    // 5. STN head (M = 1)
    lrelu_stage2(wstk + OFF_STF1, spb, t1b, 170, 341, 1, bufPD, part2, bn);
    lrelu_stage2(wstk + OFF_STF2, t1b, t2b, 85, 170, 1, bufPD, part2, bn);
    gemm8_launch(stf3_W, t2b, t3b, 21, 85, 3);

    // 6. conv2 (broadcast t3 channels) + conv3(bn only)
    lrelu_stage2m(wstk + OFF_C2, h1b, t3b, 21, h42c, 42, 42, NN, bufPD, part2, bn);
    gemm8_launch(c3_W, h42c, bufPD, 341, 42, 3*NN);
    bn_launch2(bufPD, 341, NN, (size_t)341*3*NN, part2, bn);
    combine_launch(bufPD, bufPD, bn, c3o, 341, NN, 0, (size_t)341*3*NN);

    // 7. mean over N (no concat — std1 & final read split sources)
    mean_n_kernel<<<BB*341*3, 256>>>(c3o, mn3);

    // 8. VNStdFeature (std1 with broadcast mean channels)
    lrelu_stage2m(wstk + OFF_STD1, c3o, mn3, 341, z1b, 341, 682, NN, bufPD, part2, bn);
    lrelu_stage2(wstk + OFF_STD2, z1b, s3b, 170, 341, NN, bufPD, part2, bn);
    gemm8_launch(std_lin, s3b, z0dst, 3, 170, 3*NN);

    // 9. frame projection + global max (split sources)
    final_max_kernel<<<BB*682, 128>>>(c3o, mn3, z0dst, outf);
}

// round 16
// speedup vs baseline: 1.2706x; 1.2706x over previous
#include <cuda_runtime.h>
#include <math.h>

// ---------------- problem constants ----------------
#define BB   8
#define NN   4096
#define KNB  20
#define NKK  (NN*KNB)
#define EPSV 1e-6f
#define BNEPS 1e-5f

// ---------------- static device scratch (allocation-free) ----------------
__device__ float  g_bufPD[(size_t)BB*682*3*NN];
__device__ int    g_idx [BB*NKK];
__device__ float  g_h   [BB*21*3*NN];
__device__ float  g_h1  [BB*21*3*NN];
__device__ float  g_s1  [BB*21*3*NN];
__device__ float  g_s2  [BB*42*3*NN];
__device__ float  g_s3  [BB*341*3*NN];
__device__ float  g_sp  [BB*341*3];
__device__ float  g_t1  [BB*170*3];
__device__ float  g_t2  [BB*85*3];
__device__ float  g_t3  [BB*21*3];
__device__ float  g_h42c[BB*42*3*NN];
__device__ float  g_c3o [(size_t)BB*341*3*NN];
__device__ float  g_mean3[BB*341*3];
__device__ float  g_z1  [BB*341*3*NN];
__device__ float  g_z0s [BB*3*3*NN];
__device__ float  g_bias[BB*1364*3];
__device__ double g_part2[682*64*2];
__device__ float  g_bn  [682*2];
__device__ double g_partd[21*64];
__device__ float  g_bnpos[21*2];
__device__ float  g_wstk[761604];

// stacked-weight offsets (floats)
#define OFF_C1   0
#define OFF_ST1  882
#define OFF_ST2  1764
#define OFF_ST3  3528
#define OFF_STF1 32172
#define OFF_STF2 148112
#define OFF_C2   177012
#define OFF_STD1 180540
#define OFF_STD2 645664

__global__ void stack_w_all(const float* __restrict__ a0, const float* __restrict__ b0,
                            const float* __restrict__ a1, const float* __restrict__ b1,
                            const float* __restrict__ a2, const float* __restrict__ b2,
                            const float* __restrict__ a3, const float* __restrict__ b3,
                            const float* __restrict__ a4, const float* __restrict__ b4,
                            const float* __restrict__ a5, const float* __restrict__ b5,
                            const float* __restrict__ a6, const float* __restrict__ b6,
                            const float* __restrict__ a7, const float* __restrict__ b7,
                            const float* __restrict__ a8, const float* __restrict__ b8,
                            float* __restrict__ dst) {
    const int offs[10] = {OFF_C1, OFF_ST1, OFF_ST2, OFF_ST3, OFF_STF1, OFF_STF2,
                          OFF_C2, OFF_STD1, OFF_STD2, 761604};
    const float* fa[9] = {a0,a1,a2,a3,a4,a5,a6,a7,a8};
    const float* fb[9] = {b0,b1,b2,b3,b4,b5,b6,b7,b8};
    int t = blockIdx.x * blockDim.x + threadIdx.x;
    if (t >= 761604) return;
    #pragma unroll
    for (int s = 0; s < 9; s++) {
        if (t >= offs[s] && t < offs[s+1]) {
            int loc = t - offs[s];
            int OC = (offs[s+1] - offs[s]) / 2;
            dst[t] = (loc < OC) ? fa[s][loc] : fb[s][loc - OC];
            return;
        }
    }
}

// ---------------- kNN: f32 prefilter + fp64-truth refine (FROZEN selection) -----
__global__ void knn_kernel(const float* __restrict__ x, int* __restrict__ idxout) {
    __shared__ float sx0[NN], sx1[NN], sx2[NN];
    int b = blockIdx.y;
    for (int t = threadIdx.x; t < 3*NN; t += blockDim.x) {
        float v = x[(size_t)b*3*NN + t];
        int d = t / NN, n = t - d*NN;
        if (d == 0) sx0[n] = v; else if (d == 1) sx1[n] = v; else sx2[n] = v;
    }
    __syncthreads();
    int i = blockIdx.x * blockDim.x + threadIdx.x;
    float fxi0 = sx0[i], fxi1 = sx1[i], fxi2 = sx2[i];
    float fxx = fxi0*fxi0 + fxi1*fxi1 + fxi2*fxi2;

    float fv[KNB];
    #pragma unroll
    for (int t = 0; t < KNB; t++) fv[t] = -3.0e38f;
    float fmin = -3.0e38f; int fminp = 0;
    for (int j = 0; j < NN; j++) {
        float a0 = sx0[j], a1 = sx1[j], a2 = sx2[j];
        float dot = fxi0*a0 + fxi1*a1 + fxi2*a2;
        float pd  = 2.f*dot - fxx - (a0*a0 + a1*a1 + a2*a2);
        if (pd > fmin) {
            fv[fminp] = pd; fmin = fv[0]; fminp = 0;
            #pragma unroll
            for (int t = 1; t < KNB; t++)
                if (fv[t] < fmin) { fmin = fv[t]; fminp = t; }
        }
    }
    float thr = fmin - 1e-3f;

    double xi0 = (double)fxi0, xi1 = (double)fxi1, xi2 = (double)fxi2;
    double xxi = xi0*xi0 + xi1*xi1 + xi2*xi2;
    double bv[KNB]; int bi[KNB];
    #pragma unroll
    for (int t = 0; t < KNB; t++) { bv[t] = -1.0e300; bi[t] = 0; }
    double minv = -1.0e300; int minp = 0;
    for (int j = 0; j < NN; j++) {
        float a0 = sx0[j], a1 = sx1[j], a2 = sx2[j];
        float dotf = fxi0*a0 + fxi1*a1 + fxi2*a2;
        float pdf  = 2.f*dotf - fxx - (a0*a0 + a1*a1 + a2*a2);
        if (pdf >= thr) {
            double d0 = (double)a0, d1 = (double)a1, d2 = (double)a2;
            double dot = xi0*d0 + xi1*d1 + xi2*d2;
            double pd  = 2.0*dot - xxi - (d0*d0 + d1*d1 + d2*d2);
            if (pd > minv) {
                bv[minp] = pd; bi[minp] = j;
                minv = bv[0]; minp = 0;
                #pragma unroll
                for (int t = 1; t < KNB; t++)
                    if (bv[t] < minv) { minv = bv[t]; minp = t; }
            }
        }
    }
    int* dst = idxout + ((size_t)b*NN + i)*KNB;
    #pragma unroll
    for (int t = 0; t < KNB; t++) dst[t] = bi[t];
}

// ---- XLA-replica f32 feature build (FROZEN) ------------------------------------
__device__ __forceinline__ void feat_f32(const float* __restrict__ xb, int n, int j,
                                         float* f) {
    float xi0 = xb[n],  xi1 = xb[NN + n],  xi2 = xb[2*NN + n];
    float xj0 = xb[j],  xj1 = xb[NN + j],  xj2 = xb[2*NN + j];
    f[0] = __fsub_rn(xj0, xi0); f[1] = __fsub_rn(xj1, xi1); f[2] = __fsub_rn(xj2, xi2);
    f[3] = xi0; f[4] = xi1; f[5] = xi2;
    f[6] = __fsub_rn(__fmul_rn(xj1, xi2), __fmul_rn(xj2, xi1));
    f[7] = __fsub_rn(__fmul_rn(xj2, xi0), __fmul_rn(xj0, xi2));
    f[8] = __fsub_rn(__fmul_rn(xj0, xi1), __fmul_rn(xj1, xi0));
}

__device__ __forceinline__ float dot3_fma(float w0, float w1, float w2,
                                          float f0, float f1, float f2) {
    float a = __fmul_rn(w0, f0);
    a = __fmaf_rn(w1, f1, a);
    a = __fmaf_rn(w2, f2, a);
    return a;
}

__device__ __forceinline__ float sum3_nofma(float a0, float b0, float a1, float b1,
                                            float a2, float b2) {
    return __fadd_rn(__fadd_rn(__fmul_rn(a0, b0), __fmul_rn(a1, b1)), __fmul_rn(a2, b2));
}

// ---- stage-1: materialize replica norms ONCE (FROZEN values) -------------------
__global__ void pos_norm_kernel(const float* __restrict__ x, const int* __restrict__ idx,
                                const float* __restrict__ Wf, float* __restrict__ norms) {
    const int total = BB*NKK;
    int t = blockIdx.x * blockDim.x + threadIdx.x;
    if (t >= total) return;
    int b = t / NKK, nk = t - (t / NKK)*NKK;
    int n = nk / KNB;
    int j = idx[(size_t)b*NKK + nk];
    const float* xb = x + (size_t)b*3*NN;
    float f[9]; feat_f32(xb, n, j, f);
    #pragma unroll 3
    for (int o = 0; o < 21; o++) {
        float w0 = __ldg(Wf + o*3), w1 = __ldg(Wf + o*3 + 1), w2 = __ldg(Wf + o*3 + 2);
        float p0 = dot3_fma(w0, w1, w2, f[0], f[3], f[6]);
        float p1 = dot3_fma(w0, w1, w2, f[1], f[4], f[7]);
        float p2 = dot3_fma(w0, w1, w2, f[2], f[5], f[8]);
        float nsq = sum3_nofma(p0, p0, p1, p1, p2, p2);
        float nr = __fadd_rn(__fsqrt_rn(nsq), EPSV);
        norms[(size_t)o*total + t] = nr;
    }
}

// stage-1 stats: FROZEN two-pass fp64-accumulate (bit-identical bnpos)
__global__ void bn_pos_mean(const float* __restrict__ norms, int nblk,
                            double* __restrict__ part) {
    int o = blockIdx.x, blk = blockIdx.y;
    const int total = BB*NKK;
    const float* No = norms + (size_t)o*total;
    double s = 0.0;
    for (int t = blk*blockDim.x + threadIdx.x; t < total; t += nblk*blockDim.x)
        s += (double)No[t];
    __shared__ double sh[256];
    sh[threadIdx.x] = s;
    __syncthreads();
    for (int st = 128; st > 0; st >>= 1) {
        if (threadIdx.x < st) sh[threadIdx.x] += sh[threadIdx.x+st];
        __syncthreads();
    }
    if (threadIdx.x == 0) part[(size_t)o*nblk + blk] = sh[0];
}

__global__ void bn_pos_var(const float* __restrict__ norms, const float* __restrict__ bnpos,
                           int nblk, double* __restrict__ part) {
    int o = blockIdx.x, blk = blockIdx.y;
    const int total = BB*NKK;
    const float* No = norms + (size_t)o*total;
    float mean = bnpos[o];
    double s = 0.0;
    for (int t = blk*blockDim.x + threadIdx.x; t < total; t += nblk*blockDim.x) {
        double d = (double)__fsub_rn(No[t], mean);
        s += d*d;
    }
    __shared__ double sh[256];
    sh[threadIdx.x] = s;
    __syncthreads();
    for (int st = 128; st > 0; st >>= 1) {
        if (threadIdx.x < st) sh[threadIdx.x] += sh[threadIdx.x+st];
        __syncthreads();
    }
    if (threadIdx.x == 0) part[(size_t)o*nblk + blk] = sh[0];
}

__global__ void bn_pos_final(const double* __restrict__ part, float* __restrict__ bnpos,
                             int nblk, int cnt, int pass) {
    int o = blockIdx.x;
    __shared__ double s1[64];
    double a = 0.0;
    for (int t = threadIdx.x; t < nblk; t += 64) a += part[(size_t)o*nblk + t];
    s1[threadIdx.x] = a;
    __syncthreads();
    for (int st = 32; st > 0; st >>= 1) {
        if (threadIdx.x < st) s1[threadIdx.x] += s1[threadIdx.x+st];
        __syncthreads();
    }
    if (threadIdx.x == 0) {
        if (pass == 0) bnpos[o] = (float)(s1[0] / cnt);
        else {
            float var = (float)(s1[0] / cnt);
            bnpos[21 + o] = __fsqrt_rn(__fadd_rn(var, BNEPS));
        }
    }
}

// ------- stage-1 replica pool: 4 warps/block, FROZEN per-lane arithmetic --------
__global__ void pool_k_replica(const float* __restrict__ x, const int* __restrict__ idx,
                               const float* __restrict__ Wf, const float* __restrict__ Wd,
                               const float* __restrict__ bnpos,
                               const float* __restrict__ poolWd,
                               float* __restrict__ OutH) {
    int warp = threadIdx.x / 32;
    int lane = threadIdx.x % 32;
    int bnid = blockIdx.x*4 + warp;
    int b = bnid / NN, n = bnid - b*NN;
    __shared__ float hs[4][21][3][KNB];
    __shared__ float wpool[441];
    __shared__ float wf[63], wd[63], bns[42];
    int tid = threadIdx.x;
    for (int t = tid; t < 441; t += blockDim.x) wpool[t] = poolWd[t];
    for (int t = tid; t < 63; t += blockDim.x) { wf[t] = Wf[t]; wd[t] = Wd[t]; }
    for (int t = tid; t < 42; t += blockDim.x) bns[t] = bnpos[t];
    __syncthreads();

    if (lane < KNB) {
        int k = lane;
        int j = idx[(size_t)b*NKK + (size_t)n*KNB + k];
        const float* xb = x + (size_t)b*3*NN;
        float f[9]; feat_f32(xb, n, j, f);
        for (int o = 0; o < 21; o++) {
            float a0 = wf[o*3], a1 = wf[o*3+1], a2 = wf[o*3+2];
            float p0 = dot3_fma(a0, a1, a2, f[0], f[3], f[6]);
            float p1 = dot3_fma(a0, a1, a2, f[1], f[4], f[7]);
            float p2 = dot3_fma(a0, a1, a2, f[2], f[5], f[8]);
            float nsq = sum3_nofma(p0, p0, p1, p1, p2, p2);
            float nr = __fadd_rn(__fsqrt_rn(nsq), EPSV);
            float nbn = __fdiv_rn(__fsub_rn(nr, bns[o]), bns[21 + o]);
            float q0 = __fmul_rn(__fdiv_rn(p0, nr), nbn);
            float q1 = __fmul_rn(__fdiv_rn(p1, nr), nbn);
            float q2 = __fmul_rn(__fdiv_rn(p2, nr), nbn);
            float c0 = wd[o*3], c1 = wd[o*3+1], c2 = wd[o*3+2];
            float d0 = dot3_fma(c0, c1, c2, f[0], f[3], f[6]);
            float d1 = dot3_fma(c0, c1, c2, f[1], f[4], f[7]);
            float d2 = dot3_fma(c0, c1, c2, f[2], f[5], f[8]);
            float dotv = sum3_nofma(q0, d0, q1, d1, q2, d2);
            float dsq  = sum3_nofma(d0, d0, d1, d1, d2, d2);
            if (!(dotv >= 0.f)) {
                float coef = __fdiv_rn(dotv, __fadd_rn(dsq, EPSV));
                q0 = __fsub_rn(q0, __fmul_rn(coef, d0));
                q1 = __fsub_rn(q1, __fmul_rn(coef, d1));
                q2 = __fsub_rn(q2, __fmul_rn(coef, d2));
            }
            hs[warp][o][0][k] = q0; hs[warp][o][1][k] = q1; hs[warp][o][2][k] = q2;
        }
    }
    __syncthreads();
    if (lane < 21) {
        int o = lane;
        float bestdot = -3.0e38f; int bestk = 0;
        for (int k = 0; k < KNB; k++) {
            float d0 = __fmul_rn(wpool[o*21], hs[warp][0][0][k]);
            float d1 = __fmul_rn(wpool[o*21], hs[warp][0][1][k]);
            float d2 = __fmul_rn(wpool[o*21], hs[warp][0][2][k]);
            for (int c = 1; c < 21; c++) {
                float w = wpool[o*21 + c];
                d0 = __fmaf_rn(w, hs[warp][c][0][k], d0);
                d1 = __fmaf_rn(w, hs[warp][c][1][k], d1);
                d2 = __fmaf_rn(w, hs[warp][c][2][k], d2);
            }
            float dotv = sum3_nofma(hs[warp][o][0][k], d0, hs[warp][o][1][k], d1,
                                    hs[warp][o][2][k], d2);
            if (dotv > bestdot) { bestdot = dotv; bestk = k; }
        }
        #pragma unroll
        for (int v = 0; v < 3; v++)
            OutH[((size_t)(b*21 + o)*3 + v)*NN + n] = hs[warp][o][v][bestk];
    }
}

// ------ channel GEMM: 128x128 tile, conflict-free 2x2-quad micro, double-buffer --
__global__ __launch_bounds__(256) void gemm_vn8(const float* __restrict__ W,
                                                const float* __restrict__ X,
                                                float* __restrict__ Y, int O, int C, int J) {
    const float* Xb = X + (size_t)blockIdx.z * C * J;
    float*       Yb = Y + (size_t)blockIdx.z * O * J;
    int row0 = blockIdx.y * 128;
    int col0 = blockIdx.x * 128;
    __shared__ __align__(16) float Ws[2][16][132];
    __shared__ __align__(16) float Xs[2][16][132];
    int tid = threadIdx.x;
    int tx = tid % 16, ty = tid / 16;
    int wc = tid % 16, wr8 = tid / 16;
    int xc = (tid % 32) * 4, xr = tid / 32;
    float acc[8][8] = {};
    int nkt = (C + 15) / 16;

    float wreg[8];
    float4 xreg[2];
    {
        #pragma unroll
        for (int q = 0; q < 8; q++) {
            int o = row0 + wr8*8 + q; int cc = wc;
            wreg[q] = (o < O && cc < C) ? W[(size_t)o*C + cc] : 0.f;
        }
        #pragma unroll
        for (int q = 0; q < 2; q++) {
            int cc = xr + q*8;
            xreg[q] = (cc < C) ? *(const float4*)(Xb + (size_t)cc*J + col0 + xc)
                               : make_float4(0.f, 0.f, 0.f, 0.f);
        }
        #pragma unroll
        for (int q = 0; q < 8; q++) Ws[0][wc][wr8*8 + q] = wreg[q];
        #pragma unroll
        for (int q = 0; q < 2; q++) *(float4*)&Xs[0][xr + q*8][xc] = xreg[q];
    }
    __syncthreads();

    for (int kt = 0; kt < nkt; kt++) {
        int cur = kt & 1;
        if (kt + 1 < nkt) {
            int k0 = (kt + 1) * 16;
            #pragma unroll
            for (int q = 0; q < 8; q++) {
                int o = row0 + wr8*8 + q; int cc = k0 + wc;
                wreg[q] = (o < O && cc < C) ? W[(size_t)o*C + cc] : 0.f;
            }
            #pragma unroll
            for (int q = 0; q < 2; q++) {
                int cc = k0 + xr + q*8;
                xreg[q] = (cc < C) ? *(const float4*)(Xb + (size_t)cc*J + col0 + xc)
                                   : make_float4(0.f, 0.f, 0.f, 0.f);
            }
        }
        #pragma unroll
        for (int kk = 0; kk < 16; kk++) {
            float4 wa = *(const float4*)&Ws[cur][kk][ty*4];
            float4 wb = *(const float4*)&Ws[cur][kk][64 + ty*4];
            float4 xa = *(const float4*)&Xs[cur][kk][tx*4];
            float4 xb4 = *(const float4*)&Xs[cur][kk][64 + tx*4];
            float wv[8] = {wa.x, wa.y, wa.z, wa.w, wb.x, wb.y, wb.z, wb.w};
            float xv[8] = {xa.x, xa.y, xa.z, xa.w, xb4.x, xb4.y, xb4.z, xb4.w};
            #pragma unroll
            for (int a = 0; a < 8; a++)
                #pragma unroll
                for (int bq = 0; bq < 8; bq++)
                    acc[a][bq] += wv[a]*xv[bq];
        }
        if (kt + 1 < nkt) {
            int nxt = (kt + 1) & 1;
            #pragma unroll
            for (int q = 0; q < 8; q++) Ws[nxt][wc][wr8*8 + q] = wreg[q];
            #pragma unroll
            for (int q = 0; q < 2; q++) *(float4*)&Xs[nxt][xr + q*8][xc] = xreg[q];
        }
        __syncthreads();
    }

    #pragma unroll
    for (int rg = 0; rg < 2; rg++) {
        #pragma unroll
        for (int q = 0; q < 4; q++) {
            int o = row0 + rg*64 + ty*4 + q;
            if (o < O) {
                #pragma unroll
                for (int cg = 0; cg < 2; cg++) {
                    int col = col0 + cg*64 + tx*4;
                    float4 v = make_float4(acc[rg*4+q][cg*4], acc[rg*4+q][cg*4+1],
                                           acc[rg*4+q][cg*4+2], acc[rg*4+q][cg*4+3]);
                    *(float4*)(Yb + (size_t)o*J + col) = v;
                }
            }
        }
    }
}

// bias variant: W has row stride Wstride (split lower C channels); acc starts at
// Bias[b][o][vsec] (the precomputed upper-channel contribution, constant over m).
__global__ __launch_bounds__(256) void gemm_vn8b(const float* __restrict__ W, int Wstride,
                                                 const float* __restrict__ X,
                                                 const float* __restrict__ Bias,
                                                 float* __restrict__ Y, int O, int C, int J) {
    const float* Xb = X + (size_t)blockIdx.z * C * J;
    const float* Bb = Bias + (size_t)blockIdx.z * O * 3;
    float*       Yb = Y + (size_t)blockIdx.z * O * J;
    int row0 = blockIdx.y * 128;
    int col0 = blockIdx.x * 128;
    int vsec = col0 / (J/3);
    __shared__ __align__(16) float Ws[2][16][132];
    __shared__ __align__(16) float Xs[2][16][132];
    int tid = threadIdx.x;
    int tx = tid % 16, ty = tid / 16;
    int wc = tid % 16, wr8 = tid / 16;
    int xc = (tid % 32) * 4, xr = tid / 32;
    float acc[8][8];
    #pragma unroll
    for (int rg = 0; rg < 2; rg++)
        #pragma unroll
        for (int q = 0; q < 4; q++) {
            int o = row0 + rg*64 + ty*4 + q;
            float bv = (o < O) ? Bb[o*3 + vsec] : 0.f;
            #pragma unroll
            for (int bq = 0; bq < 8; bq++) acc[rg*4+q][bq] = bv;
        }
    int nkt = (C + 15) / 16;

    float wreg[8];
    float4 xreg[2];
    {
        #pragma unroll
        for (int q = 0; q < 8; q++) {
            int o = row0 + wr8*8 + q; int cc = wc;
            wreg[q] = (o < O && cc < C) ? W[(size_t)o*Wstride + cc] : 0.f;
        }
        #pragma unroll
        for (int q = 0; q < 2; q++) {
            int cc = xr + q*8;
            xreg[q] = (cc < C) ? *(const float4*)(Xb + (size_t)cc*J + col0 + xc)
                               : make_float4(0.f, 0.f, 0.f, 0.f);
        }
        #pragma unroll
        for (int q = 0; q < 8; q++) Ws[0][wc][wr8*8 + q] = wreg[q];
        #pragma unroll
        for (int q = 0; q < 2; q++) *(float4*)&Xs[0][xr + q*8][xc] = xreg[q];
    }
    __syncthreads();

    for (int kt = 0; kt < nkt; kt++) {
        int cur = kt & 1;
        if (kt + 1 < nkt) {
            int k0 = (kt + 1) * 16;
            #pragma unroll
            for (int q = 0; q < 8; q++) {
                int o = row0 + wr8*8 + q; int cc = k0 + wc;
                wreg[q] = (o < O && cc < C) ? W[(size_t)o*Wstride + cc] : 0.f;
            }
            #pragma unroll
            for (int q = 0; q < 2; q++) {
                int cc = k0 + xr + q*8;
                xreg[q] = (cc < C) ? *(const float4*)(Xb + (size_t)cc*J + col0 + xc)
                                   : make_float4(0.f, 0.f, 0.f, 0.f);
            }
        }
        #pragma unroll
        for (int kk = 0; kk < 16; kk++) {
            float4 wa = *(const float4*)&Ws[cur][kk][ty*4];
            float4 wb = *(const float4*)&Ws[cur][kk][64 + ty*4];
            float4 xa = *(const float4*)&Xs[cur][kk][tx*4];
            float4 xb4 = *(const float4*)&Xs[cur][kk][64 + tx*4];
            float wv[8] = {wa.x, wa.y, wa.z, wa.w, wb.x, wb.y, wb.z, wb.w};
            float xv[8] = {xa.x, xa.y, xa.z, xa.w, xb4.x, xb4.y, xb4.z, xb4.w};
            #pragma unroll
            for (int a = 0; a < 8; a++)
                #pragma unroll
                for (int bq = 0; bq < 8; bq++)
                    acc[a][bq] += wv[a]*xv[bq];
        }
        if (kt + 1 < nkt) {
            int nxt = (kt + 1) & 1;
            #pragma unroll
            for (int q = 0; q < 8; q++) Ws[nxt][wc][wr8*8 + q] = wreg[q];
            #pragma unroll
            for (int q = 0; q < 2; q++) *(float4*)&Xs[nxt][xr + q*8][xc] = xreg[q];
        }
        __syncthreads();
    }

    #pragma unroll
    for (int rg = 0; rg < 2; rg++) {
        #pragma unroll
        for (int q = 0; q < 4; q++) {
            int o = row0 + rg*64 + ty*4 + q;
            if (o < O) {
                #pragma unroll
                for (int cg = 0; cg < 2; cg++) {
                    int col = col0 + cg*64 + tx*4;
                    float4 v = make_float4(acc[rg*4+q][cg*4], acc[rg*4+q][cg*4+1],
                                           acc[rg*4+q][cg*4+2], acc[rg*4+q][cg*4+3]);
                    *(float4*)(Yb + (size_t)o*J + col) = v;
                }
            }
        }
    }
}

// bias precompute: Bias[b][o][v] = sum_c W[o*Wstride + Coff + c] * Mn[b][c][v]
__global__ void bias_gemm(const float* __restrict__ W, int Wstride, int Coff, int Cup,
                          const float* __restrict__ Mn, float* __restrict__ Bias, int O) {
    int total = BB*O*3;
    int t = blockIdx.x * blockDim.x + threadIdx.x;
    if (t >= total) return;
    int v = t % 3; int r = t / 3; int o = r % O; int b = r / O;
    const float* Wo = W + (size_t)o*Wstride + Coff;
    const float* Mb = Mn + (size_t)b*Cup*3 + v;
    float acc = 0.f;
    for (int c = 0; c < Cup; c++) acc += Wo[c]*Mb[c*3];
    Bias[(size_t)b*O*3 + o*3 + v] = acc;
}

// small GEMM: one thread per output, ascending-c serial
__global__ void gemm_small(const float* __restrict__ W, const float* __restrict__ X,
                           float* __restrict__ Y, int O, int C, int J) {
    size_t total = (size_t)BB*O*J;
    size_t t = (size_t)blockIdx.x * blockDim.x + threadIdx.x;
    if (t >= total) return;
    int col = t % J; size_t r = t / J; int o = r % O; int b = r / O;
    const float* Xb = X + (size_t)b*C*J + col;
    const float* Wo = W + (size_t)o*C;
    float acc = 0.f;
    for (int c = 0; c < C; c++) acc += Wo[c]*Xb[(size_t)c*J];
    Y[(size_t)b*O*J + (size_t)o*J + col] = acc;
}

// ---------------- downstream BN stats: single pass sum+sumsq, float4 ------------
__global__ void bn_stats2v(const float* __restrict__ Y, int O, int M, size_t bstride,
                           int BM4, int nblk, double* __restrict__ part) {
    int o = blockIdx.x, blk = blockIdx.y;
    int M4 = M / 4;
    double s = 0.0, s2 = 0.0;
    for (int t = blk*blockDim.x + threadIdx.x; t < BM4; t += nblk*blockDim.x) {
        int b = t / M4; int m4 = t - b*M4;
        const float* base = Y + (size_t)b*bstride + ((size_t)o*3)*M + m4*4;
        float4 v0 = *(const float4*)(base);
        float4 v1 = *(const float4*)(base + M);
        float4 v2 = *(const float4*)(base + 2*(size_t)M);
        float nr;
        nr = sqrtf(v0.x*v0.x + v1.x*v1.x + v2.x*v2.x) + EPSV; s += (double)nr; s2 += (double)nr*(double)nr;
        nr = sqrtf(v0.y*v0.y + v1.y*v1.y + v2.y*v2.y) + EPSV; s += (double)nr; s2 += (double)nr*(double)nr;
        nr = sqrtf(v0.z*v0.z + v1.z*v1.z + v2.z*v2.z) + EPSV; s += (double)nr; s2 += (double)nr*(double)nr;
        nr = sqrtf(v0.w*v0.w + v1.w*v1.w + v2.w*v2.w) + EPSV; s += (double)nr; s2 += (double)nr*(double)nr;
    }
    __shared__ double sh1[256], sh2[256];
    sh1[threadIdx.x] = s; sh2[threadIdx.x] = s2;
    __syncthreads();
    for (int st = 128; st > 0; st >>= 1) {
        if (threadIdx.x < st) { sh1[threadIdx.x] += sh1[threadIdx.x+st]; sh2[threadIdx.x] += sh2[threadIdx.x+st]; }
        __syncthreads();
    }
    if (threadIdx.x == 0) {
        part[((size_t)o*nblk + blk)*2]     = sh1[0];
        part[((size_t)o*nblk + blk)*2 + 1] = sh2[0];
    }
}

__global__ void bn_stats2(const float* __restrict__ Y, int O, int M, size_t bstride,
                          int BMtot, int nblk, double* __restrict__ part) {
    int o = blockIdx.x, blk = blockIdx.y;
    double s = 0.0, s2 = 0.0;
    for (int t = blk*blockDim.x + threadIdx.x; t < BMtot; t += nblk*blockDim.x) {
        int b = t / M; int m = t - b*M;
        const float* base = Y + (size_t)b*bstride + ((size_t)o*3)*M + m;
        float v0 = base[0], v1 = base[M], v2 = base[2*(size_t)M];
        float nr = sqrtf(v0*v0 + v1*v1 + v2*v2) + EPSV;
        s += (double)nr; s2 += (double)nr*(double)nr;
    }
    __shared__ double sh1[256], sh2[256];
    sh1[threadIdx.x] = s; sh2[threadIdx.x] = s2;
    __syncthreads();
    for (int st = 128; st > 0; st >>= 1) {
        if (threadIdx.x < st) { sh1[threadIdx.x] += sh1[threadIdx.x+st]; sh2[threadIdx.x] += sh2[threadIdx.x+st]; }
        __syncthreads();
    }
    if (threadIdx.x == 0) {
        part[((size_t)o*nblk + blk)*2]     = sh1[0];
        part[((size_t)o*nblk + blk)*2 + 1] = sh2[0];
    }
}

__global__ void bn_final2(const double* __restrict__ part, float* __restrict__ bn,
                          int O, int nblk, int cnt) {
    int o = blockIdx.x;
    __shared__ double s1[64], s2[64];
    double a = 0.0, c = 0.0;
    for (int t = threadIdx.x; t < nblk; t += 64) {
        a += part[((size_t)o*nblk + t)*2];
        c += part[((size_t)o*nblk + t)*2 + 1];
    }
    s1[threadIdx.x] = a; s2[threadIdx.x] = c;
    __syncthreads();
    for (int st = 32; st > 0; st >>= 1) {
        if (threadIdx.x < st) { s1[threadIdx.x] += s1[threadIdx.x+st]; s2[threadIdx.x] += s2[threadIdx.x+st]; }
        __syncthreads();
    }
    if (threadIdx.x == 0) {
        double mean = s1[0] / cnt;
        double var  = s2[0] / cnt - mean*mean;
        bn[o]     = (float)mean;
        bn[O + o] = (float)(1.0 / sqrt(var + (double)BNEPS));
    }
}

// ---------------- BN apply (+ optional lrelu), float4 ---------------------------
__global__ void vn_combine4(const float* __restrict__ P, const float* __restrict__ D,
                            const float* __restrict__ bn, float* __restrict__ Out,
                            int O, int M, int lrelu, size_t bstride) {
    int M4 = M / 4;
    int total = BB*O*M4;
    int t = blockIdx.x * blockDim.x + threadIdx.x;
    if (t >= total) return;
    int m4 = t % M4; int r = t / M4; int o = r % O; int b = r / O;
    int m = m4*4;
    size_t bin = (size_t)b*bstride + ((size_t)o*3)*M + m;
    size_t bout = ((size_t)(b*O + o)*3)*M + m;
    float4 p0 = *(const float4*)(P + bin);
    float4 p1 = *(const float4*)(P + bin + M);
    float4 p2 = *(const float4*)(P + bin + 2*(size_t)M);
    float4 d0 = *(const float4*)(D + bin);
    float4 d1 = *(const float4*)(D + bin + M);
    float4 d2 = *(const float4*)(D + bin + 2*(size_t)M);
    float mean = bn[o], inv = bn[O + o];
    float o0[4], o1[4], o2[4];
    float pp0[4] = {p0.x, p0.y, p0.z, p0.w};
    float pp1[4] = {p1.x, p1.y, p1.z, p1.w};
    float pp2[4] = {p2.x, p2.y, p2.z, p2.w};
    float dd0[4] = {d0.x, d0.y, d0.z, d0.w};
    float dd1[4] = {d1.x, d1.y, d1.z, d1.w};
    float dd2[4] = {d2.x, d2.y, d2.z, d2.w};
    #pragma unroll
    for (int q = 0; q < 4; q++) {
        float q0 = pp0[q], q1 = pp1[q], q2 = pp2[q];
        float nr = sqrtf(q0*q0 + q1*q1 + q2*q2) + EPSV;
        float sc = (nr - mean) * inv / nr;
        q0 *= sc; q1 *= sc; q2 *= sc;
        if (lrelu) {
            float e0 = dd0[q], e1 = dd1[q], e2 = dd2[q];
            float dotv = q0*e0 + q1*e1 + q2*e2;
            if (dotv < 0.f) {
                float coef = dotv / (e0*e0 + e1*e1 + e2*e2 + EPSV);
                q0 -= coef*e0; q1 -= coef*e1; q2 -= coef*e2;
            }
        }
        o0[q] = q0; o1[q] = q1; o2[q] = q2;
    }
    *(float4*)(Out + bout)              = make_float4(o0[0], o0[1], o0[2], o0[3]);
    *(float4*)(Out + bout + M)          = make_float4(o1[0], o1[1], o1[2], o1[3]);
    *(float4*)(Out + bout + 2*(size_t)M)= make_float4(o2[0], o2[1], o2[2], o2[3]);
}

__global__ void vn_combine(const float* __restrict__ P, const float* __restrict__ D,
                           const float* __restrict__ bn, float* __restrict__ Out,
                           int O, int M, int lrelu, size_t bstride) {
    int total = BB*O*M;
    int t = blockIdx.x * blockDim.x + threadIdx.x;
    if (t >= total) return;
    int m = t % M; int r = t / M; int o = r % O; int b = r / O;
    size_t bin = (size_t)b*bstride + ((size_t)o*3)*M + m;
    size_t bout = ((size_t)(b*O + o)*3)*M + m;
    float p0 = P[bin], p1 = P[bin + M], p2 = P[bin + 2*(size_t)M];
    float nr = sqrtf(p0*p0 + p1*p1 + p2*p2) + EPSV;
    float sc = (nr - bn[o]) * bn[O + o] / nr;
    p0 *= sc; p1 *= sc; p2 *= sc;
    if (lrelu) {
        float d0 = D[bin], d1 = D[bin + M], d2 = D[bin + 2*(size_t)M];
        float dot = p0*d0 + p1*d1 + p2*d2;
        if (dot < 0.f) {
            float coef = dot / (d0*d0 + d1*d1 + d2*d2 + EPSV);
            p0 -= coef*d0; p1 -= coef*d1; p2 -= coef*d2;
        }
    }
    Out[bout] = p0; Out[bout + M] = p1; Out[bout + 2*(size_t)M] = p2;
}

// ---------------- VN max-pool over N (fp64 keys) ---------------------------------
__global__ void pool_n_kernel(const float* __restrict__ S, const float* __restrict__ Dv,
                              float* __restrict__ Out) {
    int bc = blockIdx.x;
    const float* Sb = S  + (size_t)bc*3*NN;
    const float* Db = Dv + (size_t)bc*3*NN;
    double bestv = -1.0e300; int besti = NN;
    for (int n = threadIdx.x; n < NN; n += 256) {
        double dot = (double)Sb[n]*(double)Db[n]
                   + (double)Sb[NN+n]*(double)Db[NN+n]
                   + (double)Sb[2*NN+n]*(double)Db[2*NN+n];
        if (dot > bestv || (dot == bestv && n < besti)) { bestv = dot; besti = n; }
    }
    __shared__ double sv[256]; __shared__ int si[256];
    sv[threadIdx.x] = bestv; si[threadIdx.x] = besti;
    __syncthreads();
    for (int st = 128; st > 0; st >>= 1) {
        if (threadIdx.x < st) {
            if (sv[threadIdx.x+st] > sv[threadIdx.x] ||
                (sv[threadIdx.x+st] == sv[threadIdx.x] && si[threadIdx.x+st] < si[threadIdx.x])) {
                sv[threadIdx.x] = sv[threadIdx.x+st]; si[threadIdx.x] = si[threadIdx.x+st];
            }
        }
        __syncthreads();
    }
    if (threadIdx.x == 0) {
        int n = si[0];
        for (int v = 0; v < 3; v++) Out[(size_t)bc*3 + v] = Sb[(size_t)v*NN + n];
    }
}

// ---------------- mean over N (float4 reads, double accumulate) ------------------
__global__ void mean_n_kernel(const float* __restrict__ X, float* __restrict__ Out) {
    int row = blockIdx.x;
    const float* Xr = X + (size_t)row*NN;
    double s = 0.0;
    for (int n4 = threadIdx.x; n4 < NN/4; n4 += 256) {
        float4 v = *(const float4*)(Xr + n4*4);
        s += (double)v.x + (double)v.y + (double)v.z + (double)v.w;
    }
    __shared__ double sh[256];
    sh[threadIdx.x] = s;
    __syncthreads();
    for (int st = 128; st > 0; st >>= 1) {
        if (threadIdx.x < st) sh[threadIdx.x] += sh[threadIdx.x+st];
        __syncthreads();
    }
    if (threadIdx.x == 0) Out[row] = (float)(sh[0] / (double)NN);
}

// --------- final: split-source (C3 rows + mean rows), float4, global max --------
__global__ void final_max_kernel(const float* __restrict__ C3, const float* __restrict__ Mn,
                                 const float* __restrict__ Z, float* __restrict__ out) {
    int bi = blockIdx.x; int b = bi / 682; int i = bi - b*682;
    const float* Zb = Z + (size_t)b*9*NN;
    float m0 = -3.0e38f, m1 = -3.0e38f, m2 = -3.0e38f;
    if (i < 341) {
        const float* Hb = C3 + ((size_t)(b*341 + i)*3)*NN;
        for (int n4 = threadIdx.x; n4 < NN/4; n4 += 128) {
            int n = n4*4;
            float4 h0 = *(const float4*)(Hb + n);
            float4 h1 = *(const float4*)(Hb + NN + n);
            float4 h2 = *(const float4*)(Hb + 2*NN + n);
            float4 z0 = *(const float4*)(Zb + 0*NN + n);
            float4 z1 = *(const float4*)(Zb + 1*NN + n);
            float4 z2 = *(const float4*)(Zb + 2*NN + n);
            float4 z3 = *(const float4*)(Zb + 3*NN + n);
            float4 z4 = *(const float4*)(Zb + 4*NN + n);
            float4 z5 = *(const float4*)(Zb + 5*NN + n);
            float4 z6 = *(const float4*)(Zb + 6*NN + n);
            float4 z7 = *(const float4*)(Zb + 7*NN + n);
            float4 z8 = *(const float4*)(Zb + 8*NN + n);
            float hh0[4] = {h0.x,h0.y,h0.z,h0.w};
            float hh1[4] = {h1.x,h1.y,h1.z,h1.w};
            float hh2[4] = {h2.x,h2.y,h2.z,h2.w};
            float zz0[4] = {z0.x,z0.y,z0.z,z0.w};
            float zz1[4] = {z1.x,z1.y,z1.z,z1.w};
            float zz2[4] = {z2.x,z2.y,z2.z,z2.w};
            float zz3[4] = {z3.x,z3.y,z3.z,z3.w};
            float zz4[4] = {z4.x,z4.y,z4.z,z4.w};
            float zz5[4] = {z5.x,z5.y,z5.z,z5.w};
            float zz6[4] = {z6.x,z6.y,z6.z,z6.w};
            float zz7[4] = {z7.x,z7.y,z7.z,z7.w};
            float zz8[4] = {z8.x,z8.y,z8.z,z8.w};
            #pragma unroll
            for (int q = 0; q < 4; q++) {
                float s0 = hh0[q]*zz0[q] + hh1[q]*zz3[q] + hh2[q]*zz6[q];
                float s1 = hh0[q]*zz1[q] + hh1[q]*zz4[q] + hh2[q]*zz7[q];
                float s2 = hh0[q]*zz2[q] + hh1[q]*zz5[q] + hh2[q]*zz8[q];
                m0 = fmaxf(m0, s0); m1 = fmaxf(m1, s1); m2 = fmaxf(m2, s2);
            }
        }
    } else {
        float hm0 = Mn[((size_t)b*341 + (i-341))*3 + 0];
        float hm1 = Mn[((size_t)b*341 + (i-341))*3 + 1];
        float hm2 = Mn[((size_t)b*341 + (i-341))*3 + 2];
        for (int n = threadIdx.x; n < NN; n += 128) {
            float s0 = hm0*Zb[0*NN+n] + hm1*Zb[3*NN+n] + hm2*Zb[6*NN+n];
            float s1 = hm0*Zb[1*NN+n] + hm1*Zb[4*NN+n] + hm2*Zb[7*NN+n];
            float s2 = hm0*Zb[2*NN+n] + hm1*Zb[5*NN+n] + hm2*Zb[8*NN+n];
            m0 = fmaxf(m0, s0); m1 = fmaxf(m1, s1); m2 = fmaxf(m2, s2);
        }
    }
    __shared__ float sm[3][128];
    sm[0][threadIdx.x] = m0; sm[1][threadIdx.x] = m1; sm[2][threadIdx.x] = m2;
    __syncthreads();
    for (int st = 64; st > 0; st >>= 1) {
        if (threadIdx.x < st) {
            sm[0][threadIdx.x] = fmaxf(sm[0][threadIdx.x], sm[0][threadIdx.x+st]);
            sm[1][threadIdx.x] = fmaxf(sm[1][threadIdx.x], sm[1][threadIdx.x+st]);
            sm[2][threadIdx.x] = fmaxf(sm[2][threadIdx.x], sm[2][threadIdx.x+st]);
        }
        __syncthreads();
    }
    if (threadIdx.x < 3) out[(size_t)b*2046 + i*3 + threadIdx.x] = sm[threadIdx.x][0];
}

// ---------------- host helpers ---------------------------------------------------
static inline int cdiv(int a, int b) { return (a + b - 1) / b; }
static float* symf(const void* s) { void* p = 0; cudaGetSymbolAddress(&p, s); return (float*)p; }

static void gemm8_launch(const float* W, const float* X, float* Y, int O, int C, int J) {
    if (O <= 24 || J < 128 || (J % 128) != 0) {
        size_t total = (size_t)BB*O*J;
        gemm_small<<<(int)((total + 255)/256), 256>>>(W, X, Y, O, C, J);
    } else {
        dim3 grid(J/128, cdiv(O, 128), BB);
        gemm_vn8<<<grid, 256>>>(W, X, Y, O, C, J);
    }
}

static void bn_launch2(const float* Y, int O, int M, size_t bstride,
                       double* part2, float* bn) {
    int BMtot = BB * M;
    int nblk = BMtot / 8192; if (nblk < 1) nblk = 1; if (nblk > 64) nblk = 64;
    if (M % 4 == 0)
        bn_stats2v<<<dim3(O, nblk), 256>>>(Y, O, M, bstride, BMtot/4, nblk, part2);
    else
        bn_stats2<<<dim3(O, nblk), 256>>>(Y, O, M, bstride, BMtot, nblk, part2);
    bn_final2<<<O, 64>>>(part2, bn, O, nblk, BMtot);
}

static void combine_launch(const float* P, const float* D, const float* bn,
                           float* Out, int O, int M, int lrelu, size_t bstride) {
    if (M % 4 == 0) {
        int total = BB * O * (M/4);
        vn_combine4<<<cdiv(total, 256), 256>>>(P, D, bn, Out, O, M, lrelu, bstride);
    } else {
        int total = BB * O * M;
        vn_combine<<<cdiv(total, 256), 256>>>(P, D, bn, Out, O, M, lrelu, bstride);
    }
}

static void lrelu_stage2(const float* Wstk, const float* X, float* outb,
                         int O, int C, int M, float* bufPD,
                         double* part2, float* bn) {
    int J = 3*M;
    gemm8_launch(Wstk, X, bufPD, 2*O, C, J);
    size_t bs = (size_t)2*O*3*M;
    bn_launch2(bufPD, O, M, bs, part2, bn);
    combine_launch(bufPD, bufPD + (size_t)O*3*M, bn, outb, O, M, 1, bs);
}

// dual stage: lower channels from Xa, upper channels folded into per-(b,o,v) bias
static void lrelu_stage2b(const float* Wstk, const float* Xa, const float* Mn,
                          int Clow, int Cfull, float* biasb, float* outb,
                          int O, int M, float* bufPD, double* part2, float* bn) {
    int J = 3*M;
    int Cup = Cfull - Clow;
    bias_gemm<<<cdiv(BB*2*O*3, 256), 256>>>(Wstk, Cfull, Clow, Cup, Mn, biasb, 2*O);
    dim3 grid(J/128, cdiv(2*O, 128), BB);
    gemm_vn8b<<<grid, 256>>>(Wstk, Cfull, Xa, biasb, bufPD, 2*O, Clow, J);
    size_t bs = (size_t)2*O*3*M;
    bn_launch2(bufPD, O, M, bs, part2, bn);
    combine_launch(bufPD, bufPD + (size_t)O*3*M, bn, outb, O, M, 1, bs);
}

extern "C" void kernel_launch(void* const* d_in, const int* in_sizes, int n_in,
                              void* d_out, int out_size) {
    const float* x          = (const float*)d_in[0];
    const float* pos_Wf     = (const float*)d_in[1];
    const float* pos_Wd     = (const float*)d_in[2];
    const float* pool_Wd    = (const float*)d_in[3];
    const float* c1_Wf      = (const float*)d_in[4];
    const float* c1_Wd      = (const float*)d_in[5];
    const float* st1_Wf     = (const float*)d_in[6];
    const float* st1_Wd     = (const float*)d_in[7];
    const float* st2_Wf     = (const float*)d_in[8];
    const float* st2_Wd     = (const float*)d_in[9];
    const float* st3_Wf     = (const float*)d_in[10];
    const float* st3_Wd     = (const float*)d_in[11];
    const float* st_pool_Wd = (const float*)d_in[12];
    const float* stf1_Wf    = (const float*)d_in[13];
    const float* stf1_Wd    = (const float*)d_in[14];
    const float* stf2_Wf    = (const float*)d_in[15];
    const float* stf2_Wd    = (const float*)d_in[16];
    const float* stf3_W     = (const float*)d_in[17];
    const float* c2_Wf      = (const float*)d_in[18];
    const float* c2_Wd      = (const float*)d_in[19];
    const float* c3_W       = (const float*)d_in[20];
    const float* std1_Wf    = (const float*)d_in[21];
    const float* std1_Wd    = (const float*)d_in[22];
    const float* std2_Wf    = (const float*)d_in[23];
    const float* std2_Wd    = (const float*)d_in[24];
    const float* std_lin    = (const float*)d_in[25];

    float*  bufPD = symf(g_bufPD);
    int*    idxp; { void* p=0; cudaGetSymbolAddress(&p, g_idx); idxp = (int*)p; }
    float*  hbuf  = symf(g_h);
    float*  h1b   = symf(g_h1);
    float*  s1b   = symf(g_s1);
    float*  s2b   = symf(g_s2);
    float*  s3b   = symf(g_s3);
    float*  spb   = symf(g_sp);
    float*  t1b   = symf(g_t1);
    float*  t2b   = symf(g_t2);
    float*  t3b   = symf(g_t3);
    float*  h42c  = symf(g_h42c);
    float*  c3o   = symf(g_c3o);
    float*  mn3   = symf(g_mean3);
    float*  z1b   = symf(g_z1);
    float*  z0sc  = symf(g_z0s);
    float*  biasb = symf(g_bias);
    float*  bn    = symf(g_bn);
    float*  bnpos = symf(g_bnpos);
    float*  wstk  = symf(g_wstk);
    double* partd;  { void* p=0; cudaGetSymbolAddress(&p, g_partd);  partd  = (double*)p; }
    double* part2;  { void* p=0; cudaGetSymbolAddress(&p, g_part2);  part2  = (double*)p; }

    float* outf = (float*)d_out;
    const int OUT1 = BB*2046;
    const int OUTZ = BB*9*NN;
    float* z0dst = (out_size >= OUT1 + OUTZ) ? (outf + OUT1) : z0sc;

    // 0. stack dual weights [Wf;Wd]
    stack_w_all<<<cdiv(761604, 256), 256>>>(c1_Wf, c1_Wd, st1_Wf, st1_Wd, st2_Wf, st2_Wd,
                                            st3_Wf, st3_Wd, stf1_Wf, stf1_Wd,
                                            stf2_Wf, stf2_Wd, c2_Wf, c2_Wd,
                                            std1_Wf, std1_Wd, std2_Wf, std2_Wd, wstk);

    // 1. kNN (f32 prefilter + fp64 refine, same selection)
    knn_kernel<<<dim3(NN/128, BB), 128>>>(x, idxp);

    // 2. stage 1 (FROZEN values): norms once, two-pass stats, replica pool
    {
        const int total = BB*NKK;
        const int nblk = 64;
        pos_norm_kernel<<<cdiv(total, 256), 256>>>(x, idxp, pos_Wf, bufPD);
        bn_pos_mean<<<dim3(21, nblk), 256>>>(bufPD, nblk, partd);
        bn_pos_final<<<21, 64>>>(partd, bnpos, nblk, total, 0);
        bn_pos_var<<<dim3(21, nblk), 256>>>(bufPD, bnpos, nblk, partd);
        bn_pos_final<<<21, 64>>>(partd, bnpos, nblk, total, 1);
        pool_k_replica<<<BB*NN/4, 128>>>(x, idxp, pos_Wf, pos_Wd, bnpos, pool_Wd, hbuf);
    }

    // 3. conv1 + STN trunk (stacked dual gemms)
    lrelu_stage2(wstk + OFF_C1,  hbuf, h1b, 21, 21, NN, bufPD, part2, bn);
    lrelu_stage2(wstk + OFF_ST1, h1b,  s1b, 21, 21, NN, bufPD, part2, bn);
    lrelu_stage2(wstk + OFF_ST2, s1b,  s2b, 42, 21, NN, bufPD, part2, bn);
    lrelu_stage2(wstk + OFF_ST3, s2b,  s3b, 341, 42, NN, bufPD, part2, bn);

    // 4. STN pool over N
    gemm8_launch(st_pool_Wd, s3b, bufPD, 341, 341, 3*NN);
    pool_n_kernel<<<BB*341, 256>>>(s3b, bufPD, spb);

    // 5. STN head (M = 1)
    lrelu_stage2(wstk + OFF_STF1, spb, t1b, 170, 341, 1, bufPD, part2, bn);
    lrelu_stage2(wstk + OFF_STF2, t1b, t2b, 85, 170, 1, bufPD, part2, bn);
    gemm8_launch(stf3_W, t2b, t3b, 21, 85, 3);

    // 6. conv2 (upper 21 channels = t3 broadcast -> bias) + conv3(bn only)
    lrelu_stage2b(wstk + OFF_C2, h1b, t3b, 21, 42, biasb, h42c, 42, NN,
                  bufPD, part2, bn);
    gemm8_launch(c3_W, h42c, bufPD, 341, 42, 3*NN);
    bn_launch2(bufPD, 341, NN, (size_t)341*3*NN, part2, bn);
    combine_launch(bufPD, bufPD, bn, c3o, 341, NN, 0, (size_t)341*3*NN);

    // 7. mean over N
    mean_n_kernel<<<BB*341*3, 256>>>(c3o, mn3);

    // 8. VNStdFeature (std1: upper 341 channels = mean3 broadcast -> bias; HALF flops)
    lrelu_stage2b(wstk + OFF_STD1, c3o, mn3, 341, 682, biasb, z1b, 341, NN,
                  bufPD, part2, bn);
    lrelu_stage2(wstk + OFF_STD2, z1b, s3b, 170, 341, NN, bufPD, part2, bn);
    gemm8_launch(std_lin, s3b, z0dst, 3, 170, 3*NN);

    // 9. frame projection + global max (split sources)
    final_max_kernel<<<BB*682, 128>>>(c3o, mn3, z0dst, outf);
}

// round 17
// speedup vs baseline: 1.2770x; 1.0050x over previous
#include <cuda_runtime.h>
#include <math.h>

// ---------------- problem constants ----------------
#define BB   8
#define NN   4096
#define KNB  20
#define NKK  (NN*KNB)
#define EPSV 1e-6f
#define BNEPS 1e-5f

// ---------------- static device scratch (allocation-free) ----------------
__device__ float  g_bufPD[(size_t)BB*682*3*NN];
__device__ int    g_idx [BB*NKK];
__device__ float  g_h   [BB*21*3*NN];
__device__ float  g_h1  [BB*21*3*NN];
__device__ float  g_s1  [BB*21*3*NN];
__device__ float  g_s2  [BB*42*3*NN];
__device__ float  g_s3  [BB*341*3*NN];
__device__ float  g_sp  [BB*341*3];
__device__ float  g_t1  [BB*170*3];
__device__ float  g_t2  [BB*85*3];
__device__ float  g_t3  [BB*21*3];
__device__ float  g_h42c[BB*42*3*NN];
__device__ float  g_c3o [(size_t)BB*341*3*NN];
__device__ float  g_mean3[BB*341*3];
__device__ float  g_z1  [BB*341*3*NN];
__device__ float  g_z0s [BB*3*3*NN];
__device__ float  g_bias[BB*1364*3];
__device__ double g_part2[682*64*2];
__device__ float  g_bn  [682*2];
__device__ double g_partd[21*64];
__device__ float  g_bnpos[21*2];
__device__ float  g_wstk[761604];

// stacked-weight offsets (floats)
#define OFF_C1   0
#define OFF_ST1  882
#define OFF_ST2  1764
#define OFF_ST3  3528
#define OFF_STF1 32172
#define OFF_STF2 148112
#define OFF_C2   177012
#define OFF_STD1 180540
#define OFF_STD2 645664

__global__ void stack_w_all(const float* __restrict__ a0, const float* __restrict__ b0,
                            const float* __restrict__ a1, const float* __restrict__ b1,
                            const float* __restrict__ a2, const float* __restrict__ b2,
                            const float* __restrict__ a3, const float* __restrict__ b3,
                            const float* __restrict__ a4, const float* __restrict__ b4,
                            const float* __restrict__ a5, const float* __restrict__ b5,
                            const float* __restrict__ a6, const float* __restrict__ b6,
                            const float* __restrict__ a7, const float* __restrict__ b7,
                            const float* __restrict__ a8, const float* __restrict__ b8,
                            float* __restrict__ dst) {
    const int offs[10] = {OFF_C1, OFF_ST1, OFF_ST2, OFF_ST3, OFF_STF1, OFF_STF2,
                          OFF_C2, OFF_STD1, OFF_STD2, 761604};
    const float* fa[9] = {a0,a1,a2,a3,a4,a5,a6,a7,a8};
    const float* fb[9] = {b0,b1,b2,b3,b4,b5,b6,b7,b8};
    int t = blockIdx.x * blockDim.x + threadIdx.x;
    if (t >= 761604) return;
    #pragma unroll
    for (int s = 0; s < 9; s++) {
        if (t >= offs[s] && t < offs[s+1]) {
            int loc = t - offs[s];
            int OC = (offs[s+1] - offs[s]) / 2;
            dst[t] = (loc < OC) ? fa[s][loc] : fb[s][loc - OC];
            return;
        }
    }
}

// ---------------- kNN: f32 prefilter + fp64-truth refine (FROZEN selection) -----
__global__ void knn_kernel(const float* __restrict__ x, int* __restrict__ idxout) {
    __shared__ float sx0[NN], sx1[NN], sx2[NN];
    int b = blockIdx.y;
    for (int t = threadIdx.x; t < 3*NN; t += blockDim.x) {
        float v = x[(size_t)b*3*NN + t];
        int d = t / NN, n = t - d*NN;
        if (d == 0) sx0[n] = v; else if (d == 1) sx1[n] = v; else sx2[n] = v;
    }
    __syncthreads();
    int i = blockIdx.x * blockDim.x + threadIdx.x;
    float fxi0 = sx0[i], fxi1 = sx1[i], fxi2 = sx2[i];
    float fxx = fxi0*fxi0 + fxi1*fxi1 + fxi2*fxi2;

    float fv[KNB];
    #pragma unroll
    for (int t = 0; t < KNB; t++) fv[t] = -3.0e38f;
    float fmin = -3.0e38f; int fminp = 0;
    for (int j = 0; j < NN; j++) {
        float a0 = sx0[j], a1 = sx1[j], a2 = sx2[j];
        float dot = fxi0*a0 + fxi1*a1 + fxi2*a2;
        float pd  = 2.f*dot - fxx - (a0*a0 + a1*a1 + a2*a2);
        if (pd > fmin) {
            fv[fminp] = pd; fmin = fv[0]; fminp = 0;
            #pragma unroll
            for (int t = 1; t < KNB; t++)
                if (fv[t] < fmin) { fmin = fv[t]; fminp = t; }
        }
    }
    float thr = fmin - 1e-3f;

    double xi0 = (double)fxi0, xi1 = (double)fxi1, xi2 = (double)fxi2;
    double xxi = xi0*xi0 + xi1*xi1 + xi2*xi2;
    double bv[KNB]; int bi[KNB];
    #pragma unroll
    for (int t = 0; t < KNB; t++) { bv[t] = -1.0e300; bi[t] = 0; }
    double minv = -1.0e300; int minp = 0;
    for (int j = 0; j < NN; j++) {
        float a0 = sx0[j], a1 = sx1[j], a2 = sx2[j];
        float dotf = fxi0*a0 + fxi1*a1 + fxi2*a2;
        float pdf  = 2.f*dotf - fxx - (a0*a0 + a1*a1 + a2*a2);
        if (pdf >= thr) {
            double d0 = (double)a0, d1 = (double)a1, d2 = (double)a2;
            double dot = xi0*d0 + xi1*d1 + xi2*d2;
            double pd  = 2.0*dot - xxi - (d0*d0 + d1*d1 + d2*d2);
            if (pd > minv) {
                bv[minp] = pd; bi[minp] = j;
                minv = bv[0]; minp = 0;
                #pragma unroll
                for (int t = 1; t < KNB; t++)
                    if (bv[t] < minv) { minv = bv[t]; minp = t; }
            }
        }
    }
    int* dst = idxout + ((size_t)b*NN + i)*KNB;
    #pragma unroll
    for (int t = 0; t < KNB; t++) dst[t] = bi[t];
}

// ---- XLA-replica f32 feature build (FROZEN) ------------------------------------
__device__ __forceinline__ void feat_f32(const float* __restrict__ xb, int n, int j,
                                         float* f) {
    float xi0 = xb[n],  xi1 = xb[NN + n],  xi2 = xb[2*NN + n];
    float xj0 = xb[j],  xj1 = xb[NN + j],  xj2 = xb[2*NN + j];
    f[0] = __fsub_rn(xj0, xi0); f[1] = __fsub_rn(xj1, xi1); f[2] = __fsub_rn(xj2, xi2);
    f[3] = xi0; f[4] = xi1; f[5] = xi2;
    f[6] = __fsub_rn(__fmul_rn(xj1, xi2), __fmul_rn(xj2, xi1));
    f[7] = __fsub_rn(__fmul_rn(xj2, xi0), __fmul_rn(xj0, xi2));
    f[8] = __fsub_rn(__fmul_rn(xj0, xi1), __fmul_rn(xj1, xi0));
}

__device__ __forceinline__ float dot3_fma(float w0, float w1, float w2,
                                          float f0, float f1, float f2) {
    float a = __fmul_rn(w0, f0);
    a = __fmaf_rn(w1, f1, a);
    a = __fmaf_rn(w2, f2, a);
    return a;
}

__device__ __forceinline__ float sum3_nofma(float a0, float b0, float a1, float b1,
                                            float a2, float b2) {
    return __fadd_rn(__fadd_rn(__fmul_rn(a0, b0), __fmul_rn(a1, b1)), __fmul_rn(a2, b2));
}

// ---- stage-1: materialize replica norms ONCE (FROZEN values) -------------------
__global__ void pos_norm_kernel(const float* __restrict__ x, const int* __restrict__ idx,
                                const float* __restrict__ Wf, float* __restrict__ norms) {
    const int total = BB*NKK;
    int t = blockIdx.x * blockDim.x + threadIdx.x;
    if (t >= total) return;
    int b = t / NKK, nk = t - (t / NKK)*NKK;
    int n = nk / KNB;
    int j = idx[(size_t)b*NKK + nk];
    const float* xb = x + (size_t)b*3*NN;
    float f[9]; feat_f32(xb, n, j, f);
    #pragma unroll 3
    for (int o = 0; o < 21; o++) {
        float w0 = __ldg(Wf + o*3), w1 = __ldg(Wf + o*3 + 1), w2 = __ldg(Wf + o*3 + 2);
        float p0 = dot3_fma(w0, w1, w2, f[0], f[3], f[6]);
        float p1 = dot3_fma(w0, w1, w2, f[1], f[4], f[7]);
        float p2 = dot3_fma(w0, w1, w2, f[2], f[5], f[8]);
        float nsq = sum3_nofma(p0, p0, p1, p1, p2, p2);
        float nr = __fadd_rn(__fsqrt_rn(nsq), EPSV);
        norms[(size_t)o*total + t] = nr;
    }
}

// stage-1 stats: FROZEN two-pass fp64-accumulate (bit-identical bnpos)
__global__ void bn_pos_mean(const float* __restrict__ norms, int nblk,
                            double* __restrict__ part) {
    int o = blockIdx.x, blk = blockIdx.y;
    const int total = BB*NKK;
    const float* No = norms + (size_t)o*total;
    double s = 0.0;
    for (int t = blk*blockDim.x + threadIdx.x; t < total; t += nblk*blockDim.x)
        s += (double)No[t];
    __shared__ double sh[256];
    sh[threadIdx.x] = s;
    __syncthreads();
    for (int st = 128; st > 0; st >>= 1) {
        if (threadIdx.x < st) sh[threadIdx.x] += sh[threadIdx.x+st];
        __syncthreads();
    }
    if (threadIdx.x == 0) part[(size_t)o*nblk + blk] = sh[0];
}

__global__ void bn_pos_var(const float* __restrict__ norms, const float* __restrict__ bnpos,
                           int nblk, double* __restrict__ part) {
    int o = blockIdx.x, blk = blockIdx.y;
    const int total = BB*NKK;
    const float* No = norms + (size_t)o*total;
    float mean = bnpos[o];
    double s = 0.0;
    for (int t = blk*blockDim.x + threadIdx.x; t < total; t += nblk*blockDim.x) {
        double d = (double)__fsub_rn(No[t], mean);
        s += d*d;
    }
    __shared__ double sh[256];
    sh[threadIdx.x] = s;
    __syncthreads();
    for (int st = 128; st > 0; st >>= 1) {
        if (threadIdx.x < st) sh[threadIdx.x] += sh[threadIdx.x+st];
        __syncthreads();
    }
    if (threadIdx.x == 0) part[(size_t)o*nblk + blk] = sh[0];
}

__global__ void bn_pos_final(const double* __restrict__ part, float* __restrict__ bnpos,
                             int nblk, int cnt, int pass) {
    int o = blockIdx.x;
    __shared__ double s1[64];
    double a = 0.0;
    for (int t = threadIdx.x; t < nblk; t += 64) a += part[(size_t)o*nblk + t];
    s1[threadIdx.x] = a;
    __syncthreads();
    for (int st = 32; st > 0; st >>= 1) {
        if (threadIdx.x < st) s1[threadIdx.x] += s1[threadIdx.x+st];
        __syncthreads();
    }
    if (threadIdx.x == 0) {
        if (pass == 0) bnpos[o] = (float)(s1[0] / cnt);
        else {
            float var = (float)(s1[0] / cnt);
            bnpos[21 + o] = __fsqrt_rn(__fadd_rn(var, BNEPS));
        }
    }
}

// ------- stage-1 replica pool: (k,o) task remap, FROZEN per-task arithmetic -----
__global__ void pool_k_replica(const float* __restrict__ x, const int* __restrict__ idx,
                               const float* __restrict__ Wf, const float* __restrict__ Wd,
                               const float* __restrict__ bnpos,
                               const float* __restrict__ poolWd,
                               float* __restrict__ OutH) {
    int warp = threadIdx.x / 32;
    int lane = threadIdx.x % 32;
    int bnid = blockIdx.x*4 + warp;
    int b = bnid / NN, n = bnid - b*NN;
    __shared__ float hs[4][21][3][KNB];
    __shared__ float fsh[4][KNB][9];
    __shared__ float wpool[441];
    __shared__ float wf[63], wd[63], bns[42];
    int tid = threadIdx.x;
    for (int t = tid; t < 441; t += blockDim.x) wpool[t] = poolWd[t];
    for (int t = tid; t < 63; t += blockDim.x) { wf[t] = Wf[t]; wd[t] = Wd[t]; }
    for (int t = tid; t < 42; t += blockDim.x) bns[t] = bnpos[t];
    __syncthreads();

    // phase A: features per k (frozen feat_f32)
    if (lane < KNB) {
        int k = lane;
        int j = idx[(size_t)b*NKK + (size_t)n*KNB + k];
        const float* xb = x + (size_t)b*3*NN;
        float f[9]; feat_f32(xb, n, j, f);
        #pragma unroll
        for (int q = 0; q < 9; q++) fsh[warp][k][q] = f[q];
    }
    __syncwarp();

    // phase B: 420 independent (k,o) tasks across all 32 lanes (frozen per-task math)
    for (int t = lane; t < KNB*21; t += 32) {
        int k = t / 21, o = t - (t / 21)*21;
        float f[9];
        #pragma unroll
        for (int q = 0; q < 9; q++) f[q] = fsh[warp][k][q];
        float a0 = wf[o*3], a1 = wf[o*3+1], a2 = wf[o*3+2];
        float p0 = dot3_fma(a0, a1, a2, f[0], f[3], f[6]);
        float p1 = dot3_fma(a0, a1, a2, f[1], f[4], f[7]);
        float p2 = dot3_fma(a0, a1, a2, f[2], f[5], f[8]);
        float nsq = sum3_nofma(p0, p0, p1, p1, p2, p2);
        float nr = __fadd_rn(__fsqrt_rn(nsq), EPSV);
        float nbn = __fdiv_rn(__fsub_rn(nr, bns[o]), bns[21 + o]);
        float q0 = __fmul_rn(__fdiv_rn(p0, nr), nbn);
        float q1 = __fmul_rn(__fdiv_rn(p1, nr), nbn);
        float q2 = __fmul_rn(__fdiv_rn(p2, nr), nbn);
        float c0 = wd[o*3], c1 = wd[o*3+1], c2 = wd[o*3+2];
        float d0 = dot3_fma(c0, c1, c2, f[0], f[3], f[6]);
        float d1 = dot3_fma(c0, c1, c2, f[1], f[4], f[7]);
        float d2 = dot3_fma(c0, c1, c2, f[2], f[5], f[8]);
        float dotv = sum3_nofma(q0, d0, q1, d1, q2, d2);
        float dsq  = sum3_nofma(d0, d0, d1, d1, d2, d2);
        if (!(dotv >= 0.f)) {
            float coef = __fdiv_rn(dotv, __fadd_rn(dsq, EPSV));
            q0 = __fsub_rn(q0, __fmul_rn(coef, d0));
            q1 = __fsub_rn(q1, __fmul_rn(coef, d1));
            q2 = __fsub_rn(q2, __fmul_rn(coef, d2));
        }
        hs[warp][o][0][k] = q0; hs[warp][o][1][k] = q1; hs[warp][o][2][k] = q2;
    }
    __syncwarp();

    // phase C: argmax (FROZEN)
    if (lane < 21) {
        int o = lane;
        float bestdot = -3.0e38f; int bestk = 0;
        for (int k = 0; k < KNB; k++) {
            float d0 = __fmul_rn(wpool[o*21], hs[warp][0][0][k]);
            float d1 = __fmul_rn(wpool[o*21], hs[warp][0][1][k]);
            float d2 = __fmul_rn(wpool[o*21], hs[warp][0][2][k]);
            for (int c = 1; c < 21; c++) {
                float w = wpool[o*21 + c];
                d0 = __fmaf_rn(w, hs[warp][c][0][k], d0);
                d1 = __fmaf_rn(w, hs[warp][c][1][k], d1);
                d2 = __fmaf_rn(w, hs[warp][c][2][k], d2);
            }
            float dotv = sum3_nofma(hs[warp][o][0][k], d0, hs[warp][o][1][k], d1,
                                    hs[warp][o][2][k], d2);
            if (dotv > bestdot) { bestdot = dotv; bestk = k; }
        }
        #pragma unroll
        for (int v = 0; v < 3; v++)
            OutH[((size_t)(b*21 + o)*3 + v)*NN + n] = hs[warp][o][v][bestk];
    }
}

// ------ channel GEMM: 128x128 tile, KT=32, conflict-free quads, double-buffer ---
// Per-element k-order ascending (bit-identical to KT=16 version).
__global__ __launch_bounds__(256, 2) void gemm_vn8(const float* __restrict__ W,
                                                   const float* __restrict__ X,
                                                   float* __restrict__ Y,
                                                   int O, int C, int J) {
    const float* Xb = X + (size_t)blockIdx.z * C * J;
    float*       Yb = Y + (size_t)blockIdx.z * O * J;
    int row0 = blockIdx.y * 128;
    int col0 = blockIdx.x * 128;
    __shared__ __align__(16) float Ws[2][32][132];
    __shared__ __align__(16) float Xs[2][32][132];
    int tid = threadIdx.x;
    int tx = tid % 16, ty = tid / 16;
    int wc = tid % 32, wr = tid / 32;           // W: 8 groups x 16 rows
    int xc = (tid % 32) * 4, xr = tid / 32;     // X: cc = xr + q*8, q<4
    float acc[8][8] = {};
    int nkt = (C + 31) / 32;

    float wreg[16];
    float4 xreg[4];
    {
        #pragma unroll
        for (int q = 0; q < 16; q++) {
            int o = row0 + wr*16 + q; int cc = wc;
            wreg[q] = (o < O && cc < C) ? W[(size_t)o*C + cc] : 0.f;
        }
        #pragma unroll
        for (int q = 0; q < 4; q++) {
            int cc = xr + q*8;
            xreg[q] = (cc < C) ? *(const float4*)(Xb + (size_t)cc*J + col0 + xc)
                               : make_float4(0.f, 0.f, 0.f, 0.f);
        }
        #pragma unroll
        for (int q = 0; q < 16; q++) Ws[0][wc][wr*16 + q] = wreg[q];
        #pragma unroll
        for (int q = 0; q < 4; q++) *(float4*)&Xs[0][xr + q*8][xc] = xreg[q];
    }
    __syncthreads();

    for (int kt = 0; kt < nkt; kt++) {
        int cur = kt & 1;
        if (kt + 1 < nkt) {
            int k0 = (kt + 1) * 32;
            #pragma unroll
            for (int q = 0; q < 16; q++) {
                int o = row0 + wr*16 + q; int cc = k0 + wc;
                wreg[q] = (o < O && cc < C) ? W[(size_t)o*C + cc] : 0.f;
            }
            #pragma unroll
            for (int q = 0; q < 4; q++) {
                int cc = k0 + xr + q*8;
                xreg[q] = (cc < C) ? *(const float4*)(Xb + (size_t)cc*J + col0 + xc)
                                   : make_float4(0.f, 0.f, 0.f, 0.f);
            }
        }
        #pragma unroll
        for (int kk = 0; kk < 32; kk++) {
            float4 wa = *(const float4*)&Ws[cur][kk][ty*4];
            float4 wb = *(const float4*)&Ws[cur][kk][64 + ty*4];
            float4 xa = *(const float4*)&Xs[cur][kk][tx*4];
            float4 xb4 = *(const float4*)&Xs[cur][kk][64 + tx*4];
            float wv[8] = {wa.x, wa.y, wa.z, wa.w, wb.x, wb.y, wb.z, wb.w};
            float xv[8] = {xa.x, xa.y, xa.z, xa.w, xb4.x, xb4.y, xb4.z, xb4.w};
            #pragma unroll
            for (int a = 0; a < 8; a++)
                #pragma unroll
                for (int bq = 0; bq < 8; bq++)
                    acc[a][bq] += wv[a]*xv[bq];
        }
        if (kt + 1 < nkt) {
            int nxt = (kt + 1) & 1;
            #pragma unroll
            for (int q = 0; q < 16; q++) Ws[nxt][wc][wr*16 + q] = wreg[q];
            #pragma unroll
            for (int q = 0; q < 4; q++) *(float4*)&Xs[nxt][xr + q*8][xc] = xreg[q];
        }
        __syncthreads();
    }

    #pragma unroll
    for (int rg = 0; rg < 2; rg++) {
        #pragma unroll
        for (int q = 0; q < 4; q++) {
            int o = row0 + rg*64 + ty*4 + q;
            if (o < O) {
                #pragma unroll
                for (int cg = 0; cg < 2; cg++) {
                    int col = col0 + cg*64 + tx*4;
                    float4 v = make_float4(acc[rg*4+q][cg*4], acc[rg*4+q][cg*4+1],
                                           acc[rg*4+q][cg*4+2], acc[rg*4+q][cg*4+3]);
                    *(float4*)(Yb + (size_t)o*J + col) = v;
                }
            }
        }
    }
}

// bias variant: W row stride Wstride; acc starts at Bias[b][o][vsec]; KT=32
__global__ __launch_bounds__(256, 2) void gemm_vn8b(const float* __restrict__ W, int Wstride,
                                                    const float* __restrict__ X,
                                                    const float* __restrict__ Bias,
                                                    float* __restrict__ Y,
                                                    int O, int C, int J) {
    const float* Xb = X + (size_t)blockIdx.z * C * J;
    const float* Bb = Bias + (size_t)blockIdx.z * O * 3;
    float*       Yb = Y + (size_t)blockIdx.z * O * J;
    int row0 = blockIdx.y * 128;
    int col0 = blockIdx.x * 128;
    int vsec = col0 / (J/3);
    __shared__ __align__(16) float Ws[2][32][132];
    __shared__ __align__(16) float Xs[2][32][132];
    int tid = threadIdx.x;
    int tx = tid % 16, ty = tid / 16;
    int wc = tid % 32, wr = tid / 32;
    int xc = (tid % 32) * 4, xr = tid / 32;
    float acc[8][8];
    #pragma unroll
    for (int rg = 0; rg < 2; rg++)
        #pragma unroll
        for (int q = 0; q < 4; q++) {
            int o = row0 + rg*64 + ty*4 + q;
            float bv = (o < O) ? Bb[o*3 + vsec] : 0.f;
            #pragma unroll
            for (int bq = 0; bq < 8; bq++) acc[rg*4+q][bq] = bv;
        }
    int nkt = (C + 31) / 32;

    float wreg[16];
    float4 xreg[4];
    {
        #pragma unroll
        for (int q = 0; q < 16; q++) {
            int o = row0 + wr*16 + q; int cc = wc;
            wreg[q] = (o < O && cc < C) ? W[(size_t)o*Wstride + cc] : 0.f;
        }
        #pragma unroll
        for (int q = 0; q < 4; q++) {
            int cc = xr + q*8;
            xreg[q] = (cc < C) ? *(const float4*)(Xb + (size_t)cc*J + col0 + xc)
                               : make_float4(0.f, 0.f, 0.f, 0.f);
        }
        #pragma unroll
        for (int q = 0; q < 16; q++) Ws[0][wc][wr*16 + q] = wreg[q];
        #pragma unroll
        for (int q = 0; q < 4; q++) *(float4*)&Xs[0][xr + q*8][xc] = xreg[q];
    }
    __syncthreads();

    for (int kt = 0; kt < nkt; kt++) {
        int cur = kt & 1;
        if (kt + 1 < nkt) {
            int k0 = (kt + 1) * 32;
            #pragma unroll
            for (int q = 0; q < 16; q++) {
                int o = row0 + wr*16 + q; int cc = k0 + wc;
                wreg[q] = (o < O && cc < C) ? W[(size_t)o*Wstride + cc] : 0.f;
            }
            #pragma unroll
            for (int q = 0; q < 4; q++) {
                int cc = k0 + xr + q*8;
                xreg[q] = (cc < C) ? *(const float4*)(Xb + (size_t)cc*J + col0 + xc)
                                   : make_float4(0.f, 0.f, 0.f, 0.f);
            }
        }
        #pragma unroll
        for (int kk = 0; kk < 32; kk++) {
            float4 wa = *(const float4*)&Ws[cur][kk][ty*4];
            float4 wb = *(const float4*)&Ws[cur][kk][64 + ty*4];
            float4 xa = *(const float4*)&Xs[cur][kk][tx*4];
            float4 xb4 = *(const float4*)&Xs[cur][kk][64 + tx*4];
            float wv[8] = {wa.x, wa.y, wa.z, wa.w, wb.x, wb.y, wb.z, wb.w};
            float xv[8] = {xa.x, xa.y, xa.z, xa.w, xb4.x, xb4.y, xb4.z, xb4.w};
            #pragma unroll
            for (int a = 0; a < 8; a++)
                #pragma unroll
                for (int bq = 0; bq < 8; bq++)
                    acc[a][bq] += wv[a]*xv[bq];
        }
        if (kt + 1 < nkt) {
            int nxt = (kt + 1) & 1;
            #pragma unroll
            for (int q = 0; q < 16; q++) Ws[nxt][wc][wr*16 + q] = wreg[q];
            #pragma unroll
            for (int q = 0; q < 4; q++) *(float4*)&Xs[nxt][xr + q*8][xc] = xreg[q];
        }
        __syncthreads();
    }

    #pragma unroll
    for (int rg = 0; rg < 2; rg++) {
        #pragma unroll
        for (int q = 0; q < 4; q++) {
            int o = row0 + rg*64 + ty*4 + q;
            if (o < O) {
                #pragma unroll
                for (int cg = 0; cg < 2; cg++) {
                    int col = col0 + cg*64 + tx*4;
                    float4 v = make_float4(acc[rg*4+q][cg*4], acc[rg*4+q][cg*4+1],
                                           acc[rg*4+q][cg*4+2], acc[rg*4+q][cg*4+3]);
                    *(float4*)(Yb + (size_t)o*J + col) = v;
                }
            }
        }
    }
}

// bias precompute: Bias[b][o][v] = sum_c W[o*Wstride + Coff + c] * Mn[b][c][v]
__global__ void bias_gemm(const float* __restrict__ W, int Wstride, int Coff, int Cup,
                          const float* __restrict__ Mn, float* __restrict__ Bias, int O) {
    int total = BB*O*3;
    int t = blockIdx.x * blockDim.x + threadIdx.x;
    if (t >= total) return;
    int v = t % 3; int r = t / 3; int o = r % O; int b = r / O;
    const float* Wo = W + (size_t)o*Wstride + Coff;
    const float* Mb = Mn + (size_t)b*Cup*3 + v;
    float acc = 0.f;
    for (int c = 0; c < Cup; c++) acc += Wo[c]*Mb[c*3];
    Bias[(size_t)b*O*3 + o*3 + v] = acc;
}

// small GEMM: one thread per output, ascending-c serial
__global__ void gemm_small(const float* __restrict__ W, const float* __restrict__ X,
                           float* __restrict__ Y, int O, int C, int J) {
    size_t total = (size_t)BB*O*J;
    size_t t = (size_t)blockIdx.x * blockDim.x + threadIdx.x;
    if (t >= total) return;
    int col = t % J; size_t r = t / J; int o = r % O; int b = r / O;
    const float* Xb = X + (size_t)b*C*J + col;
    const float* Wo = W + (size_t)o*C;
    float acc = 0.f;
    for (int c = 0; c < C; c++) acc += Wo[c]*Xb[(size_t)c*J];
    Y[(size_t)b*O*J + (size_t)o*J + col] = acc;
}

// ---------------- downstream BN stats: single pass sum+sumsq, float4 ------------
__global__ void bn_stats2v(const float* __restrict__ Y, int O, int M, size_t bstride,
                           int BM4, int nblk, double* __restrict__ part) {
    int o = blockIdx.x, blk = blockIdx.y;
    int M4 = M / 4;
    double s = 0.0, s2 = 0.0;
    for (int t = blk*blockDim.x + threadIdx.x; t < BM4; t += nblk*blockDim.x) {
        int b = t / M4; int m4 = t - b*M4;
        const float* base = Y + (size_t)b*bstride + ((size_t)o*3)*M + m4*4;
        float4 v0 = *(const float4*)(base);
        float4 v1 = *(const float4*)(base + M);
        float4 v2 = *(const float4*)(base + 2*(size_t)M);
        float nr;
        nr = sqrtf(v0.x*v0.x + v1.x*v1.x + v2.x*v2.x) + EPSV; s += (double)nr; s2 += (double)nr*(double)nr;
        nr = sqrtf(v0.y*v0.y + v1.y*v1.y + v2.y*v2.y) + EPSV; s += (double)nr; s2 += (double)nr*(double)nr;
        nr = sqrtf(v0.z*v0.z + v1.z*v1.z + v2.z*v2.z) + EPSV; s += (double)nr; s2 += (double)nr*(double)nr;
        nr = sqrtf(v0.w*v0.w + v1.w*v1.w + v2.w*v2.w) + EPSV; s += (double)nr; s2 += (double)nr*(double)nr;
    }
    __shared__ double sh1[256], sh2[256];
    sh1[threadIdx.x] = s; sh2[threadIdx.x] = s2;
    __syncthreads();
    for (int st = 128; st > 0; st >>= 1) {
        if (threadIdx.x < st) { sh1[threadIdx.x] += sh1[threadIdx.x+st]; sh2[threadIdx.x] += sh2[threadIdx.x+st]; }
        __syncthreads();
    }
    if (threadIdx.x == 0) {
        part[((size_t)o*nblk + blk)*2]     = sh1[0];
        part[((size_t)o*nblk + blk)*2 + 1] = sh2[0];
    }
}

__global__ void bn_stats2(const float* __restrict__ Y, int O, int M, size_t bstride,
                          int BMtot, int nblk, double* __restrict__ part) {
    int o = blockIdx.x, blk = blockIdx.y;
    double s = 0.0, s2 = 0.0;
    for (int t = blk*blockDim.x + threadIdx.x; t < BMtot; t += nblk*blockDim.x) {
        int b = t / M; int m = t - b*M;
        const float* base = Y + (size_t)b*bstride + ((size_t)o*3)*M + m;
        float v0 = base[0], v1 = base[M], v2 = base[2*(size_t)M];
        float nr = sqrtf(v0*v0 + v1*v1 + v2*v2) + EPSV;
        s += (double)nr; s2 += (double)nr*(double)nr;
    }
    __shared__ double sh1[256], sh2[256];
    sh1[threadIdx.x] = s; sh2[threadIdx.x] = s2;
    __syncthreads();
    for (int st = 128; st > 0; st >>= 1) {
        if (threadIdx.x < st) { sh1[threadIdx.x] += sh1[threadIdx.x+st]; sh2[threadIdx.x] += sh2[threadIdx.x+st]; }
        __syncthreads();
    }
    if (threadIdx.x == 0) {
        part[((size_t)o*nblk + blk)*2]     = sh1[0];
        part[((size_t)o*nblk + blk)*2 + 1] = sh2[0];
    }
}

__global__ void bn_final2(const double* __restrict__ part, float* __restrict__ bn,
                          int O, int nblk, int cnt) {
    int o = blockIdx.x;
    __shared__ double s1[64], s2[64];
    double a = 0.0, c = 0.0;
    for (int t = threadIdx.x; t < nblk; t += 64) {
        a += part[((size_t)o*nblk + t)*2];
        c += part[((size_t)o*nblk + t)*2 + 1];
    }
    s1[threadIdx.x] = a; s2[threadIdx.x] = c;
    __syncthreads();
    for (int st = 32; st > 0; st >>= 1) {
        if (threadIdx.x < st) { s1[threadIdx.x] += s1[threadIdx.x+st]; s2[threadIdx.x] += s2[threadIdx.x+st]; }
        __syncthreads();
    }
    if (threadIdx.x == 0) {
        double mean = s1[0] / cnt;
        double var  = s2[0] / cnt - mean*mean;
        bn[o]     = (float)mean;
        bn[O + o] = (float)(1.0 / sqrt(var + (double)BNEPS));
    }
}

// ---------------- BN apply (+ optional lrelu), float4 ---------------------------
__global__ void vn_combine4(const float* __restrict__ P, const float* __restrict__ D,
                            const float* __restrict__ bn, float* __restrict__ Out,
                            int O, int M, int lrelu, size_t bstride) {
    int M4 = M / 4;
    int total = BB*O*M4;
    int t = blockIdx.x * blockDim.x + threadIdx.x;
    if (t >= total) return;
    int m4 = t % M4; int r = t / M4; int o = r % O; int b = r / O;
    int m = m4*4;
    size_t bin = (size_t)b*bstride + ((size_t)o*3)*M + m;
    size_t bout = ((size_t)(b*O + o)*3)*M + m;
    float4 p0 = *(const float4*)(P + bin);
    float4 p1 = *(const float4*)(P + bin + M);
    float4 p2 = *(const float4*)(P + bin + 2*(size_t)M);
    float4 d0 = *(const float4*)(D + bin);
    float4 d1 = *(const float4*)(D + bin + M);
    float4 d2 = *(const float4*)(D + bin + 2*(size_t)M);
    float mean = bn[o], inv = bn[O + o];
    float o0[4], o1[4], o2[4];
    float pp0[4] = {p0.x, p0.y, p0.z, p0.w};
    float pp1[4] = {p1.x, p1.y, p1.z, p1.w};
    float pp2[4] = {p2.x, p2.y, p2.z, p2.w};
    float dd0[4] = {d0.x, d0.y, d0.z, d0.w};
    float dd1[4] = {d1.x, d1.y, d1.z, d1.w};
    float dd2[4] = {d2.x, d2.y, d2.z, d2.w};
    #pragma unroll
    for (int q = 0; q < 4; q++) {
        float q0 = pp0[q], q1 = pp1[q], q2 = pp2[q];
        float nr = sqrtf(q0*q0 + q1*q1 + q2*q2) + EPSV;
        float sc = (nr - mean) * inv / nr;
        q0 *= sc; q1 *= sc; q2 *= sc;
        if (lrelu) {
            float e0 = dd0[q], e1 = dd1[q], e2 = dd2[q];
            float dotv = q0*e0 + q1*e1 + q2*e2;
            if (dotv < 0.f) {
                float coef = dotv / (e0*e0 + e1*e1 + e2*e2 + EPSV);
                q0 -= coef*e0; q1 -= coef*e1; q2 -= coef*e2;
            }
        }
        o0[q] = q0; o1[q] = q1; o2[q] = q2;
    }
    *(float4*)(Out + bout)              = make_float4(o0[0], o0[1], o0[2], o0[3]);
    *(float4*)(Out + bout + M)          = make_float4(o1[0], o1[1], o1[2], o1[3]);
    *(float4*)(Out + bout + 2*(size_t)M)= make_float4(o2[0], o2[1], o2[2], o2[3]);
}

__global__ void vn_combine(const float* __restrict__ P, const float* __restrict__ D,
                           const float* __restrict__ bn, float* __restrict__ Out,
                           int O, int M, int lrelu, size_t bstride) {
    int total = BB*O*M;
    int t = blockIdx.x * blockDim.x + threadIdx.x;
    if (t >= total) return;
    int m = t % M; int r = t / M; int o = r % O; int b = r / O;
    size_t bin = (size_t)b*bstride + ((size_t)o*3)*M + m;
    size_t bout = ((size_t)(b*O + o)*3)*M + m;
    float p0 = P[bin], p1 = P[bin + M], p2 = P[bin + 2*(size_t)M];
    float nr = sqrtf(p0*p0 + p1*p1 + p2*p2) + EPSV;
    float sc = (nr - bn[o]) * bn[O + o] / nr;
    p0 *= sc; p1 *= sc; p2 *= sc;
    if (lrelu) {
        float d0 = D[bin], d1 = D[bin + M], d2 = D[bin + 2*(size_t)M];
        float dot = p0*d0 + p1*d1 + p2*d2;
        if (dot < 0.f) {
            float coef = dot / (d0*d0 + d1*d1 + d2*d2 + EPSV);
            p0 -= coef*d0; p1 -= coef*d1; p2 -= coef*d2;
        }
    }
    Out[bout] = p0; Out[bout + M] = p1; Out[bout + 2*(size_t)M] = p2;
}

// ---------------- VN max-pool over N (fp64 keys) ---------------------------------
__global__ void pool_n_kernel(const float* __restrict__ S, const float* __restrict__ Dv,
                              float* __restrict__ Out) {
    int bc = blockIdx.x;
    const float* Sb = S  + (size_t)bc*3*NN;
    const float* Db = Dv + (size_t)bc*3*NN;
    double bestv = -1.0e300; int besti = NN;
    for (int n = threadIdx.x; n < NN; n += 256) {
        double dot = (double)Sb[n]*(double)Db[n]
                   + (double)Sb[NN+n]*(double)Db[NN+n]
                   + (double)Sb[2*NN+n]*(double)Db[2*NN+n];
        if (dot > bestv || (dot == bestv && n < besti)) { bestv = dot; besti = n; }
    }
    __shared__ double sv[256]; __shared__ int si[256];
    sv[threadIdx.x] = bestv; si[threadIdx.x] = besti;
    __syncthreads();
    for (int st = 128; st > 0; st >>= 1) {
        if (threadIdx.x < st) {
            if (sv[threadIdx.x+st] > sv[threadIdx.x] ||
                (sv[threadIdx.x+st] == sv[threadIdx.x] && si[threadIdx.x+st] < si[threadIdx.x])) {
                sv[threadIdx.x] = sv[threadIdx.x+st]; si[threadIdx.x] = si[threadIdx.x+st];
            }
        }
        __syncthreads();
    }
    if (threadIdx.x == 0) {
        int n = si[0];
        for (int v = 0; v < 3; v++) Out[(size_t)bc*3 + v] = Sb[(size_t)v*NN + n];
    }
}

// ---------------- mean over N (float4 reads, double accumulate) ------------------
__global__ void mean_n_kernel(const float* __restrict__ X, float* __restrict__ Out) {
    int row = blockIdx.x;
    const float* Xr = X + (size_t)row*NN;
    double s = 0.0;
    for (int n4 = threadIdx.x; n4 < NN/4; n4 += 256) {
        float4 v = *(const float4*)(Xr + n4*4);
        s += (double)v.x + (double)v.y + (double)v.z + (double)v.w;
    }
    __shared__ double sh[256];
    sh[threadIdx.x] = s;
    __syncthreads();
    for (int st = 128; st > 0; st >>= 1) {
        if (threadIdx.x < st) sh[threadIdx.x] += sh[threadIdx.x+st];
        __syncthreads();
    }
    if (threadIdx.x == 0) Out[row] = (float)(sh[0] / (double)NN);
}

// --------- final: split-source (C3 rows + mean rows), float4, global max --------
__global__ void final_max_kernel(const float* __restrict__ C3, const float* __restrict__ Mn,
                                 const float* __restrict__ Z, float* __restrict__ out) {
    int bi = blockIdx.x; int b = bi / 682; int i = bi - b*682;
    const float* Zb = Z + (size_t)b*9*NN;
    float m0 = -3.0e38f, m1 = -3.0e38f, m2 = -3.0e38f;
    if (i < 341) {
        const float* Hb = C3 + ((size_t)(b*341 + i)*3)*NN;
        for (int n4 = threadIdx.x; n4 < NN/4; n4 += 128) {
            int n = n4*4;
            float4 h0 = *(const float4*)(Hb + n);
            float4 h1 = *(const float4*)(Hb + NN + n);
            float4 h2 = *(const float4*)(Hb + 2*NN + n);
            float4 z0 = *(const float4*)(Zb + 0*NN + n);
            float4 z1 = *(const float4*)(Zb + 1*NN + n);
            float4 z2 = *(const float4*)(Zb + 2*NN + n);
            float4 z3 = *(const float4*)(Zb + 3*NN + n);
            float4 z4 = *(const float4*)(Zb + 4*NN + n);
            float4 z5 = *(const float4*)(Zb + 5*NN + n);
            float4 z6 = *(const float4*)(Zb + 6*NN + n);
            float4 z7 = *(const float4*)(Zb + 7*NN + n);
            float4 z8 = *(const float4*)(Zb + 8*NN + n);
            float hh0[4] = {h0.x,h0.y,h0.z,h0.w};
            float hh1[4] = {h1.x,h1.y,h1.z,h1.w};
            float hh2[4] = {h2.x,h2.y,h2.z,h2.w};
            float zz0[4] = {z0.x,z0.y,z0.z,z0.w};
            float zz1[4] = {z1.x,z1.y,z1.z,z1.w};
            float zz2[4] = {z2.x,z2.y,z2.z,z2.w};
            float zz3[4] = {z3.x,z3.y,z3.z,z3.w};
            float zz4[4] = {z4.x,z4.y,z4.z,z4.w};
            float zz5[4] = {z5.x,z5.y,z5.z,z5.w};
            float zz6[4] = {z6.x,z6.y,z6.z,z6.w};
            float zz7[4] = {z7.x,z7.y,z7.z,z7.w};
            float zz8[4] = {z8.x,z8.y,z8.z,z8.w};
            #pragma unroll
            for (int q = 0; q < 4; q++) {
                float s0 = hh0[q]*zz0[q] + hh1[q]*zz3[q] + hh2[q]*zz6[q];
                float s1 = hh0[q]*zz1[q] + hh1[q]*zz4[q] + hh2[q]*zz7[q];
                float s2 = hh0[q]*zz2[q] + hh1[q]*zz5[q] + hh2[q]*zz8[q];
                m0 = fmaxf(m0, s0); m1 = fmaxf(m1, s1); m2 = fmaxf(m2, s2);
            }
        }
    } else {
        float hm0 = Mn[((size_t)b*341 + (i-341))*3 + 0];
        float hm1 = Mn[((size_t)b*341 + (i-341))*3 + 1];
        float hm2 = Mn[((size_t)b*341 + (i-341))*3 + 2];
        for (int n = threadIdx.x; n < NN; n += 128) {
            float s0 = hm0*Zb[0*NN+n] + hm1*Zb[3*NN+n] + hm2*Zb[6*NN+n];
            float s1 = hm0*Zb[1*NN+n] + hm1*Zb[4*NN+n] + hm2*Zb[7*NN+n];
            float s2 = hm0*Zb[2*NN+n] + hm1*Zb[5*NN+n] + hm2*Zb[8*NN+n];
            m0 = fmaxf(m0, s0); m1 = fmaxf(m1, s1); m2 = fmaxf(m2, s2);
        }
    }
    __shared__ float sm[3][128];
    sm[0][threadIdx.x] = m0; sm[1][threadIdx.x] = m1; sm[2][threadIdx.x] = m2;
    __syncthreads();
    for (int st = 64; st > 0; st >>= 1) {
        if (threadIdx.x < st) {
            sm[0][threadIdx.x] = fmaxf(sm[0][threadIdx.x], sm[0][threadIdx.x+st]);
            sm[1][threadIdx.x] = fmaxf(sm[1][threadIdx.x], sm[1][threadIdx.x+st]);
            sm[2][threadIdx.x] = fmaxf(sm[2][threadIdx.x], sm[2][threadIdx.x+st]);
        }
        __syncthreads();
    }
    if (threadIdx.x < 3) out[(size_t)b*2046 + i*3 + threadIdx.x] = sm[threadIdx.x][0];
}

// ---------------- host helpers ---------------------------------------------------
static inline int cdiv(int a, int b) { return (a + b - 1) / b; }
static float* symf(const void* s) { void* p = 0; cudaGetSymbolAddress(&p, s); return (float*)p; }

static void gemm8_launch(const float* W, const float* X, float* Y, int O, int C, int J) {
    if (O <= 24 || J < 128 || (J % 128) != 0) {
        size_t total = (size_t)BB*O*J;
        gemm_small<<<(int)((total + 255)/256), 256>>>(W, X, Y, O, C, J);
    } else {
        dim3 grid(J/128, cdiv(O, 128), BB);
        gemm_vn8<<<grid, 256>>>(W, X, Y, O, C, J);
    }
}

static void bn_launch2(const float* Y, int O, int M, size_t bstride,
                       double* part2, float* bn) {
    int BMtot = BB * M;
    int nblk = BMtot / 8192; if (nblk < 1) nblk = 1; if (nblk > 64) nblk = 64;
    if (M % 4 == 0)
        bn_stats2v<<<dim3(O, nblk), 256>>>(Y, O, M, bstride, BMtot/4, nblk, part2);
    else
        bn_stats2<<<dim3(O, nblk), 256>>>(Y, O, M, bstride, BMtot, nblk, part2);
    bn_final2<<<O, 64>>>(part2, bn, O, nblk, BMtot);
}

static void combine_launch(const float* P, const float* D, const float* bn,
                           float* Out, int O, int M, int lrelu, size_t bstride) {
    if (M % 4 == 0) {
        int total = BB * O * (M/4);
        vn_combine4<<<cdiv(total, 256), 256>>>(P, D, bn, Out, O, M, lrelu, bstride);
    } else {
        int total = BB * O * M;
        vn_combine<<<cdiv(total, 256), 256>>>(P, D, bn, Out, O, M, lrelu, bstride);
    }
}

static void lrelu_stage2(const float* Wstk, const float* X, float* outb,
                         int O, int C, int M, float* bufPD,
                         double* part2, float* bn) {
    int J = 3*M;
    gemm8_launch(Wstk, X, bufPD, 2*O, C, J);
    size_t bs = (size_t)2*O*3*M;
    bn_launch2(bufPD, O, M, bs, part2, bn);
    combine_launch(bufPD, bufPD + (size_t)O*3*M, bn, outb, O, M, 1, bs);
}

// dual stage: lower channels from Xa, upper channels folded into per-(b,o,v) bias
static void lrelu_stage2b(const float* Wstk, const float* Xa, const float* Mn,
                          int Clow, int Cfull, float* biasb, float* outb,
                          int O, int M, float* bufPD, double* part2, float* bn) {
    int J = 3*M;
    int Cup = Cfull - Clow;
    bias_gemm<<<cdiv(BB*2*O*3, 256), 256>>>(Wstk, Cfull, Clow, Cup, Mn, biasb, 2*O);
    dim3 grid(J/128, cdiv(2*O, 128), BB);
    gemm_vn8b<<<grid, 256>>>(Wstk, Cfull, Xa, biasb, bufPD, 2*O, Clow, J);
    size_t bs = (size_t)2*O*3*M;
    bn_launch2(bufPD, O, M, bs, part2, bn);
    combine_launch(bufPD, bufPD + (size_t)O*3*M, bn, outb, O, M, 1, bs);
}

extern "C" void kernel_launch(void* const* d_in, const int* in_sizes, int n_in,
                              void* d_out, int out_size) {
    const float* x          = (const float*)d_in[0];
    const float* pos_Wf     = (const float*)d_in[1];
    const float* pos_Wd     = (const float*)d_in[2];
    const float* pool_Wd    = (const float*)d_in[3];
    const float* c1_Wf      = (const float*)d_in[4];
    const float* c1_Wd      = (const float*)d_in[5];
    const float* st1_Wf     = (const float*)d_in[6];
    const float* st1_Wd     = (const float*)d_in[7];
    const float* st2_Wf     = (const float*)d_in[8];
    const float* st2_Wd     = (const float*)d_in[9];
    const float* st3_Wf     = (const float*)d_in[10];
    const float* st3_Wd     = (const float*)d_in[11];
    const float* st_pool_Wd = (const float*)d_in[12];
    const float* stf1_Wf    = (const float*)d_in[13];
    const float* stf1_Wd    = (const float*)d_in[14];
    const float* stf2_Wf    = (const float*)d_in[15];
    const float* stf2_Wd    = (const float*)d_in[16];
    const float* stf3_W     = (const float*)d_in[17];
    const float* c2_Wf      = (const float*)d_in[18];
    const float* c2_Wd      = (const float*)d_in[19];
    const float* c3_W       = (const float*)d_in[20];
    const float* std1_Wf    = (const float*)d_in[21];
    const float* std1_Wd    = (const float*)d_in[22];
    const float* std2_Wf    = (const float*)d_in[23];
    const float* std2_Wd    = (const float*)d_in[24];
    const float* std_lin    = (const float*)d_in[25];

    float*  bufPD = symf(g_bufPD);
    int*    idxp; { void* p=0; cudaGetSymbolAddress(&p, g_idx); idxp = (int*)p; }
    float*  hbuf  = symf(g_h);
    float*  h1b   = symf(g_h1);
    float*  s1b   = symf(g_s1);
    float*  s2b   = symf(g_s2);
    float*  s3b   = symf(g_s3);
    float*  spb   = symf(g_sp);
    float*  t1b   = symf(g_t1);
    float*  t2b   = symf(g_t2);
    float*  t3b   = symf(g_t3);
    float*  h42c  = symf(g_h42c);
    float*  c3o   = symf(g_c3o);
    float*  mn3   = symf(g_mean3);
    float*  z1b   = symf(g_z1);
    float*  z0sc  = symf(g_z0s);
    float*  biasb = symf(g_bias);
    float*  bn    = symf(g_bn);
    float*  bnpos = symf(g_bnpos);
    float*  wstk  = symf(g_wstk);
    double* partd;  { void* p=0; cudaGetSymbolAddress(&p, g_partd);  partd  = (double*)p; }
    double* part2;  { void* p=0; cudaGetSymbolAddress(&p, g_part2);  part2  = (double*)p; }

    float* outf = (float*)d_out;
    const int OUT1 = BB*2046;
    const int OUTZ = BB*9*NN;
    float* z0dst = (out_size >= OUT1 + OUTZ) ? (outf + OUT1) : z0sc;

    // 0. stack dual weights [Wf;Wd]
    stack_w_all<<<cdiv(761604, 256), 256>>>(c1_Wf, c1_Wd, st1_Wf, st1_Wd, st2_Wf, st2_Wd,
                                            st3_Wf, st3_Wd, stf1_Wf, stf1_Wd,
                                            stf2_Wf, stf2_Wd, c2_Wf, c2_Wd,
                                            std1_Wf, std1_Wd, std2_Wf, std2_Wd, wstk);

    // 1. kNN (f32 prefilter + fp64 refine, same selection)
    knn_kernel<<<dim3(NN/128, BB), 128>>>(x, idxp);

    // 2. stage 1 (FROZEN values): norms once, two-pass stats, replica pool
    {
        const int total = BB*NKK;
        const int nblk = 64;
        pos_norm_kernel<<<cdiv(total, 256), 256>>>(x, idxp, pos_Wf, bufPD);
        bn_pos_mean<<<dim3(21, nblk), 256>>>(bufPD, nblk, partd);
        bn_pos_final<<<21, 64>>>(partd, bnpos, nblk, total, 0);
        bn_pos_var<<<dim3(21, nblk), 256>>>(bufPD, bnpos, nblk, partd);
        bn_pos_final<<<21, 64>>>(partd, bnpos, nblk, total, 1);
        pool_k_replica<<<BB*NN/4, 128>>>(x, idxp, pos_Wf, pos_Wd, bnpos, pool_Wd, hbuf);
    }

    // 3. conv1 + STN trunk (stacked dual gemms)
    lrelu_stage2(wstk + OFF_C1,  hbuf, h1b, 21, 21, NN, bufPD, part2, bn);
    lrelu_stage2(wstk + OFF_ST1, h1b,  s1b, 21, 21, NN, bufPD, part2, bn);
    lrelu_stage2(wstk + OFF_ST2, s1b,  s2b, 42, 21, NN, bufPD, part2, bn);
    lrelu_stage2(wstk + OFF_ST3, s2b,  s3b, 341, 42, NN, bufPD, part2, bn);

    // 4. STN pool over N
    gemm8_launch(st_pool_Wd, s3b, bufPD, 341, 341, 3*NN);
    pool_n_kernel<<<BB*341, 256>>>(s3b, bufPD, spb);

    // 5. STN head (M = 1)
    lrelu_stage2(wstk + OFF_STF1, spb, t1b, 170, 341, 1, bufPD, part2, bn);
    lrelu_stage2(wstk + OFF_STF2, t1b, t2b, 85, 170, 1, bufPD, part2, bn);
    gemm8_launch(stf3_W, t2b, t3b, 21, 85, 3);

    // 6. conv2 (upper 21 channels = t3 broadcast -> bias) + conv3(bn only)
    lrelu_stage2b(wstk + OFF_C2, h1b, t3b, 21, 42, biasb, h42c, 42, NN,
                  bufPD, part2, bn);
    gemm8_launch(c3_W, h42c, bufPD, 341, 42, 3*NN);
    bn_launch2(bufPD, 341, NN, (size_t)341*3*NN, part2, bn);
    combine_launch(bufPD, bufPD, bn, c3o, 341, NN, 0, (size_t)341*3*NN);

    // 7. mean over N
    mean_n_kernel<<<BB*341*3, 256>>>(c3o, mn3);

    // 8. VNStdFeature (std1: upper 341 channels = mean3 broadcast -> bias)
    lrelu_stage2b(wstk + OFF_STD1, c3o, mn3, 341, 682, biasb, z1b, 341, NN,
                  bufPD, part2, bn);
    lrelu_stage2(wstk + OFF_STD2, z1b, s3b, 170, 341, NN, bufPD, part2, bn);
    gemm8_launch(std_lin, s3b, z0dst, 3, 170, 3*NN);

    // 9. frame projection + global max (split sources)
    final_max_kernel<<<BB*682, 128>>>(c3o, mn3, z0dst, outf);
}